// round 9
// baseline (speedup 1.0000x reference)
#include <cuda_runtime.h>
#include <cuda_bf16.h>
#include <math.h>
#include <stdint.h>

#define N_NODES 4096
#define F_IN    256
#define F_OUT   512
#define HEADS   8
#define DH      64
#define LOG2E   1.4426950408889634f

#define KTILE   64
#define NSPLIT  2
#define NT_S    (N_NODES / KTILE / NSPLIT)   // 32 key tiles per split
#define QTILE   128                 // q rows per block (32 per warp)
#define PITCH   144                 // bytes per 64-bf16 row (16B aligned, conflict-free)
#define STG     (KTILE * PITCH)     // 9216 bytes per array
#define STAGE_SZ (2 * STG)          // Kh + Kl per stage (18432)

// ---------------- device scratch (no allocs allowed) ----------------
__device__ __align__(256) float         g_h [N_NODES * F_OUT];
__device__ __align__(256) __nv_bfloat16 g_hh[N_NODES * F_OUT];
__device__ __align__(256) __nv_bfloat16 g_hl[N_NODES * F_OUT];
__device__ __align__(256) __nv_bfloat16 g_qh[N_NODES * F_OUT];
__device__ __align__(256) __nv_bfloat16 g_ql[N_NODES * F_OUT];
__device__ __align__(256) float         g_opart[NSPLIT][N_NODES * F_OUT];   // unnormalized partial O
__device__ __align__(256) float         g_lpart[NSPLIT][N_NODES * HEADS];   // partial softmax denominators

// ---------------- helpers ----------------
__device__ __forceinline__ uint32_t smem_u32(const void* p) {
    uint32_t a;
    asm("{ .reg .u64 t; cvta.to.shared.u64 t, %1; cvt.u32.u64 %0, t; }" : "=r"(a) : "l"(p));
    return a;
}
__device__ __forceinline__ uint32_t bfpk(float a, float b) {
    uint32_t r; asm("cvt.rn.bf16x2.f32 %0, %1, %2;" : "=r"(r) : "f"(b), "f"(a)); return r;
}
// FFMA-pipe exp2 (no MUFU)
__device__ __forceinline__ float exp2_fast(float x) {
    const float MAGIC = 12582912.0f;        // 1.5 * 2^23
    float fn = x + MAGIC;
    int   n  = __float_as_int(fn);
    float t  = fn - MAGIC;
    float f  = x - t;                       // [-0.5, 0.5]
    float p  = 0.0013333558f;
    p = fmaf(p, f, 0.0096181291f);
    p = fmaf(p, f, 0.0555041087f);
    p = fmaf(p, f, 0.2402265070f);
    p = fmaf(p, f, 0.6931471806f);
    p = fmaf(p, f, 1.0f);
    return __int_as_float(__float_as_int(p) + (n << 23));
}
__device__ __forceinline__ void cpa16(uint32_t dst, const void* src) {
    asm volatile("cp.async.cg.shared.global [%0], [%1], 16;" :: "r"(dst), "l"(src) : "memory");
}
#define CP_COMMIT() asm volatile("cp.async.commit_group;" ::: "memory")
#define CP_WAIT0()  asm volatile("cp.async.wait_group 0;" ::: "memory")

__device__ __forceinline__ void ldsm4(uint32_t a, uint32_t& r0, uint32_t& r1,
                                      uint32_t& r2, uint32_t& r3) {
    asm volatile("ldmatrix.sync.aligned.m8n8.x4.shared.b16 {%0,%1,%2,%3}, [%4];"
                 : "=r"(r0), "=r"(r1), "=r"(r2), "=r"(r3) : "r"(a));
}
__device__ __forceinline__ void ldsm4t(uint32_t a, uint32_t& r0, uint32_t& r1,
                                       uint32_t& r2, uint32_t& r3) {
    asm volatile("ldmatrix.sync.aligned.m8n8.x4.trans.shared.b16 {%0,%1,%2,%3}, [%4];"
                 : "=r"(r0), "=r"(r1), "=r"(r2), "=r"(r3) : "r"(a));
}
__device__ __forceinline__ void mma16816(float* c, const uint32_t* a, uint32_t b0, uint32_t b1) {
    asm volatile(
        "mma.sync.aligned.m16n8k16.row.col.f32.bf16.bf16.f32 "
        "{%0,%1,%2,%3}, {%4,%5,%6,%7}, {%8,%9}, {%0,%1,%2,%3};"
        : "+f"(c[0]), "+f"(c[1]), "+f"(c[2]), "+f"(c[3])
        : "r"(a[0]), "r"(a[1]), "r"(a[2]), "r"(a[3]), "r"(b0), "r"(b1));
}

// ---------------------------------------------------------------------------
// Kernel 1: h = x @ W^T, fp32; epilogue also writes bf16 hi/lo split.
// ---------------------------------------------------------------------------
__global__ __launch_bounds__(256) void k_gemm_xwT(const float* __restrict__ X,
                                                  const float* __restrict__ W) {
    __shared__ float sX[16][68];
    __shared__ float sW[16][68];
    const int tid = threadIdx.x;
    const int ty = tid >> 4, tx = tid & 15;
    const int m0 = blockIdx.x * 64, n0 = blockIdx.y * 64;

    float acc[4][4] = {};
    for (int k0 = 0; k0 < F_IN; k0 += 16) {
        {
            const int r  = tid >> 2;
            const int kk = (tid & 3) * 4;
            float4 v = *(const float4*)&X[(m0 + r) * F_IN + k0 + kk];
            sX[kk + 0][r] = v.x; sX[kk + 1][r] = v.y;
            sX[kk + 2][r] = v.z; sX[kk + 3][r] = v.w;
            float4 w = *(const float4*)&W[(n0 + r) * F_IN + k0 + kk];
            sW[kk + 0][r] = w.x; sW[kk + 1][r] = w.y;
            sW[kk + 2][r] = w.z; sW[kk + 3][r] = w.w;
        }
        __syncthreads();
        #pragma unroll
        for (int kk = 0; kk < 16; kk++) {
            float a[4], b[4];
            #pragma unroll
            for (int i = 0; i < 4; i++) a[i] = sX[kk][ty * 4 + i];
            #pragma unroll
            for (int j = 0; j < 4; j++) b[j] = sW[kk][tx * 4 + j];
            #pragma unroll
            for (int i = 0; i < 4; i++)
                #pragma unroll
                for (int j = 0; j < 4; j++)
                    acc[i][j] = fmaf(a[i], b[j], acc[i][j]);
        }
        __syncthreads();
    }
    #pragma unroll
    for (int i = 0; i < 4; i++) {
        const int idx = (m0 + ty * 4 + i) * F_OUT + n0 + tx * 4;
        *(float4*)&g_h[idx] = make_float4(acc[i][0], acc[i][1], acc[i][2], acc[i][3]);
        #pragma unroll
        for (int jp = 0; jp < 2; jp++) {
            float v0 = acc[i][2 * jp], v1 = acc[i][2 * jp + 1];
            uint32_t hp = bfpk(v0, v1);
            float r0 = v0 - __uint_as_float(hp << 16);
            float r1 = v1 - __uint_as_float(hp & 0xFFFF0000u);
            *(uint32_t*)&g_hh[idx + 2 * jp] = hp;
            *(uint32_t*)&g_hl[idx + 2 * jp] = bfpk(r0, r1);
        }
    }
}

// ---------------------------------------------------------------------------
// Kernel 2: q = h @ A (per head), scaled by log2(e), written as bf16 hi/lo.
// ---------------------------------------------------------------------------
__global__ __launch_bounds__(256) void k_gemm_hA(const float* __restrict__ A) {
    __shared__ float sH[64][65];
    __shared__ float sA[64][65];
    const int tid = threadIdx.x;
    const int ty = tid >> 4, tx = tid & 15;
    const int head = blockIdx.y;
    const int n0 = blockIdx.x * 64;

    {
        const int r  = tid >> 2;
        const int c0 = (tid & 3) * 16;
        #pragma unroll
        for (int cc = 0; cc < 16; cc += 4) {
            float4 v = *(const float4*)&g_h[(n0 + r) * F_OUT + head * DH + c0 + cc];
            sH[c0 + cc + 0][r] = v.x; sH[c0 + cc + 1][r] = v.y;
            sH[c0 + cc + 2][r] = v.z; sH[c0 + cc + 3][r] = v.w;
            float4 a = *(const float4*)&A[head * DH * DH + r * DH + c0 + cc];
            sA[r][c0 + cc + 0] = a.x; sA[r][c0 + cc + 1] = a.y;
            sA[r][c0 + cc + 2] = a.z; sA[r][c0 + cc + 3] = a.w;
        }
    }
    __syncthreads();

    float acc[4][4] = {};
    #pragma unroll 16
    for (int d = 0; d < DH; d++) {
        float a[4], b[4];
        #pragma unroll
        for (int i = 0; i < 4; i++) a[i] = sH[d][ty * 4 + i];
        #pragma unroll
        for (int j = 0; j < 4; j++) b[j] = sA[d][tx * 4 + j];
        #pragma unroll
        for (int i = 0; i < 4; i++)
            #pragma unroll
            for (int j = 0; j < 4; j++)
                acc[i][j] = fmaf(a[i], b[j], acc[i][j]);
    }
    #pragma unroll
    for (int i = 0; i < 4; i++) {
        const int idx = (n0 + ty * 4 + i) * F_OUT + head * DH + tx * 4;
        #pragma unroll
        for (int jp = 0; jp < 2; jp++) {
            float v0 = acc[i][2 * jp] * LOG2E, v1 = acc[i][2 * jp + 1] * LOG2E;
            uint32_t hp = bfpk(v0, v1);
            float r0 = v0 - __uint_as_float(hp << 16);
            float r1 = v1 - __uint_as_float(hp & 0xFFFF0000u);
            *(uint32_t*)&g_qh[idx + 2 * jp] = hp;
            *(uint32_t*)&g_ql[idx + 2 * jp] = bfpk(r0, r1);
        }
    }
}

// ---------------------------------------------------------------------------
// Kernel 3: flash attention partials via mma.sync; 2-way key split so 3 blocks
// co-reside per SM (3 warps/SMSP). Warp owns 32 q rows (2 m16 tiles per
// B-fragment). Writes UNNORMALIZED partial O + partial lsum (exact combine:
// no max subtraction anywhere).
// ---------------------------------------------------------------------------
__global__ __launch_bounds__(128, 3) void k_attn() {
    __shared__ __align__(16) char smem[2 * STAGE_SZ];   // 36864 B (also Q staging)
    const uint32_t sb = smem_u32(smem);

    const int tid   = threadIdx.x;
    const int w     = tid >> 5;
    const int lane  = tid & 31;
    const int head  = blockIdx.y;
    const int split = blockIdx.z;
    const int q0    = blockIdx.x * QTILE;
    const int key00 = split * (N_NODES / NSPLIT);
    const int hb    = head * DH;

    // ldmatrix per-lane address constants
    const int lm = lane >> 3, lr = lane & 7;
    const int sKey = ((lm >> 1) << 3) + lr;   // S-B: key row offset
    const int sD   = (lm & 1) << 3;           // S-B: d col offset
    const int vKey = ((lm & 1) << 3) + lr;    // V-B(trans): key row offset
    const int vD   = (lm >> 1) << 3;          // V-B(trans): dim col offset
    const int qRow = ((lm & 1) << 3) + lr;    // Q-A: row offset within 16-row tile
    const int qCol = (lm >> 1) << 3;

    // ---- stage Q (hi at sb, lo at sb+STAGE_SZ) in the K-stage area ----
    {
        const int r = tid;                     // 0..127 -> q row
        const __nv_bfloat16* qh = &g_qh[(size_t)(q0 + r) * F_OUT + hb];
        const __nv_bfloat16* ql = &g_ql[(size_t)(q0 + r) * F_OUT + hb];
        const uint32_t d0 = sb + r * PITCH;
        #pragma unroll
        for (int c = 0; c < 8; c++) cpa16(d0 + c * 16, qh + c * 8);
        const uint32_t d1 = sb + STAGE_SZ + r * PITCH;
        #pragma unroll
        for (int c = 0; c < 8; c++) cpa16(d1 + c * 16, ql + c * 8);
    }
    CP_COMMIT();
    CP_WAIT0();
    __syncthreads();

    // Q A-fragments: [s*2+m] for k-step s (0..3), m-tile m (0..1); hi and lo
    uint32_t qa[8][4], qb[8][4];
    #pragma unroll
    for (int m = 0; m < 2; m++) {
        const uint32_t qbh = sb + (w * 32 + m * 16 + qRow) * PITCH + qCol * 2;
        const uint32_t qbl = qbh + STAGE_SZ;
        #pragma unroll
        for (int s = 0; s < 4; s++) {
            ldsm4(qbh + 16 * s * 2, qa[s * 2 + m][0], qa[s * 2 + m][1],
                                    qa[s * 2 + m][2], qa[s * 2 + m][3]);
            ldsm4(qbl + 16 * s * 2, qb[s * 2 + m][0], qb[s * 2 + m][1],
                                    qb[s * 2 + m][2], qb[s * 2 + m][3]);
        }
    }
    __syncthreads();   // Q staging area now free for K tiles

    // ---- prologue: load K tile 0 of this split into stage 0 ----
    {
        const int r = tid >> 1, cb = (tid & 1) * 4;
        const uint32_t d0 = sb + r * PITCH + cb * 16;
        const __nv_bfloat16* kh = &g_hh[(size_t)(key00 + r) * F_OUT + hb];
        const __nv_bfloat16* kl = &g_hl[(size_t)(key00 + r) * F_OUT + hb];
        #pragma unroll
        for (int c = 0; c < 4; c++) cpa16(d0 + c * 16, kh + (cb + c) * 8);
        #pragma unroll
        for (int c = 0; c < 4; c++) cpa16(d0 + STG + c * 16, kl + (cb + c) * 8);
    }
    CP_COMMIT();

    float oc[2][8][4];
    #pragma unroll
    for (int m = 0; m < 2; m++)
        #pragma unroll
        for (int j = 0; j < 8; j++)
            #pragma unroll
            for (int k = 0; k < 4; k++) oc[m][j][k] = 0.f;
    float lsum[2][2] = {};   // [m][half]: rows g / g+8

    for (int t = 0; t < NT_S; t++) {
        CP_WAIT0();
        __syncthreads();
        const uint32_t stg = sb + (t & 1) * STAGE_SZ;

        // prefetch next tile into other stage
        if (t + 1 < NT_S) {
            const int r = tid >> 1, cb = (tid & 1) * 4;
            const uint32_t d0 = sb + ((t + 1) & 1) * STAGE_SZ + r * PITCH + cb * 16;
            const __nv_bfloat16* kh = &g_hh[(size_t)(key00 + (t + 1) * KTILE + r) * F_OUT + hb];
            const __nv_bfloat16* kl = &g_hl[(size_t)(key00 + (t + 1) * KTILE + r) * F_OUT + hb];
            #pragma unroll
            for (int c = 0; c < 4; c++) cpa16(d0 + c * 16, kh + (cb + c) * 8);
            #pragma unroll
            for (int c = 0; c < 4; c++) cpa16(d0 + STG + c * 16, kl + (cb + c) * 8);
        }
        CP_COMMIT();

        const uint32_t sAddr = stg + sKey * PITCH + sD * 2;
        const uint32_t vAddr = stg + vKey * PITCH + vD * 2;

        // ---- per-16-key block: S -> softmax -> PV ----
        #pragma unroll
        for (int u = 0; u < 4; u++) {
            // S = Q K^T (3-mma compensated), both m-tiles per B-fragment
            float sc[2][2][4];
            #pragma unroll
            for (int m = 0; m < 2; m++)
                #pragma unroll
                for (int k = 0; k < 4; k++) { sc[m][0][k] = 0.f; sc[m][1][k] = 0.f; }

            #pragma unroll
            for (int s = 0; s < 4; s++) {
                const uint32_t a = sAddr + (16 * u) * PITCH + (16 * s) * 2;
                uint32_t h0, h1, h2, h3, l0, l1, l2, l3;
                ldsm4(a,       h0, h1, h2, h3);
                ldsm4(a + STG, l0, l1, l2, l3);
                #pragma unroll
                for (int m = 0; m < 2; m++) {
                    mma16816(sc[m][0], qa[s * 2 + m], h0, h1);
                    mma16816(sc[m][1], qa[s * 2 + m], h2, h3);
                    mma16816(sc[m][0], qa[s * 2 + m], l0, l1);
                    mma16816(sc[m][1], qa[s * 2 + m], l2, l3);
                    mma16816(sc[m][0], qb[s * 2 + m], h0, h1);
                    mma16816(sc[m][1], qb[s * 2 + m], h2, h3);
                }
            }

            // softmax + build P hi/lo A-fragments
            uint32_t pah[2][4], pal[2][4];
            #pragma unroll
            for (int m = 0; m < 2; m++) {
                float e[8];
                #pragma unroll
                for (int k = 0; k < 4; k++) {
                    float v0 = sc[m][0][k];
                    e[k] = exp2_fast(fmaxf(v0, 0.2f * v0));
                    float v1 = sc[m][1][k];
                    e[4 + k] = exp2_fast(fmaxf(v1, 0.2f * v1));
                }
                lsum[m][0] += (e[0] + e[1]) + (e[4] + e[5]);
                lsum[m][1] += (e[2] + e[3]) + (e[6] + e[7]);

                pah[m][0] = bfpk(e[0], e[1]);
                pah[m][1] = bfpk(e[2], e[3]);
                pah[m][2] = bfpk(e[4], e[5]);
                pah[m][3] = bfpk(e[6], e[7]);
                pal[m][0] = bfpk(e[0] - __uint_as_float(pah[m][0] << 16),
                                 e[1] - __uint_as_float(pah[m][0] & 0xFFFF0000u));
                pal[m][1] = bfpk(e[2] - __uint_as_float(pah[m][1] << 16),
                                 e[3] - __uint_as_float(pah[m][1] & 0xFFFF0000u));
                pal[m][2] = bfpk(e[4] - __uint_as_float(pah[m][2] << 16),
                                 e[5] - __uint_as_float(pah[m][2] & 0xFFFF0000u));
                pal[m][3] = bfpk(e[6] - __uint_as_float(pah[m][3] << 16),
                                 e[7] - __uint_as_float(pah[m][3] & 0xFFFF0000u));
            }

            // O += P V (V = K tile, trans ldmatrix), both m-tiles per B-fragment
            #pragma unroll
            for (int d = 0; d < 4; d++) {
                const uint32_t a = vAddr + (16 * u) * PITCH + (16 * d) * 2;
                uint32_t h0, h1, h2, h3, l0, l1, l2, l3;
                ldsm4t(a,       h0, h1, h2, h3);
                ldsm4t(a + STG, l0, l1, l2, l3);
                #pragma unroll
                for (int m = 0; m < 2; m++) {
                    mma16816(oc[m][2 * d],     pah[m], h0, h1);
                    mma16816(oc[m][2 * d + 1], pah[m], h2, h3);
                    mma16816(oc[m][2 * d],     pah[m], l0, l1);
                    mma16816(oc[m][2 * d + 1], pah[m], l2, l3);
                    mma16816(oc[m][2 * d],     pal[m], h0, h1);
                    mma16816(oc[m][2 * d + 1], pal[m], h2, h3);
                }
            }
        }
    }

    // ---- reduce lsum across quad; write UNNORMALIZED partials ----
    const int g  = lane >> 2, tg = lane & 3;
    float* opart = g_opart[split];
    float* lpart = g_lpart[split];
    #pragma unroll
    for (int m = 0; m < 2; m++) {
        float lA = lsum[m][0], lB = lsum[m][1];
        lA += __shfl_xor_sync(0xffffffffu, lA, 1);
        lA += __shfl_xor_sync(0xffffffffu, lA, 2);
        lB += __shfl_xor_sync(0xffffffffu, lB, 1);
        lB += __shfl_xor_sync(0xffffffffu, lB, 2);

        const int rowA = q0 + w * 32 + m * 16 + g;
        const int rowB = rowA + 8;
        if (tg == 0) {
            lpart[rowA * HEADS + head] = lA;
            lpart[rowB * HEADS + head] = lB;
        }
        float* outA = &opart[(size_t)rowA * F_OUT + hb + 2 * tg];
        float* outB = outA + 8 * F_OUT;
        #pragma unroll
        for (int j = 0; j < 8; j++) {
            *(float2*)(outA + 8 * j) = make_float2(oc[m][j][0], oc[m][j][1]);
            *(float2*)(outB + 8 * j) = make_float2(oc[m][j][2], oc[m][j][3]);
        }
    }
}

// ---------------------------------------------------------------------------
// Kernel 4: combine key-split partials: out = (O0 + O1) / (l0 + l1)
// ---------------------------------------------------------------------------
__global__ __launch_bounds__(256) void k_combine(float* __restrict__ Out) {
    const int i4 = blockIdx.x * 256 + threadIdx.x;   // float4 index
    const int i  = i4 * 4;
    const int row  = i >> 9;            // / F_OUT
    const int col  = i & (F_OUT - 1);
    const int head = col >> 6;          // / DH
    const float l = g_lpart[0][row * HEADS + head] + g_lpart[1][row * HEADS + head];
    const float inv = 1.0f / l;
    float4 a = *(const float4*)&g_opart[0][i];
    float4 b = *(const float4*)&g_opart[1][i];
    float4 o = make_float4((a.x + b.x) * inv, (a.y + b.y) * inv,
                           (a.z + b.z) * inv, (a.w + b.w) * inv);
    *(float4*)&Out[i] = o;
}

// ---------------------------------------------------------------------------
extern "C" void kernel_launch(void* const* d_in, const int* in_sizes, int n_in,
                              void* d_out, int out_size) {
    const float* x = (const float*)d_in[0];
    // d_in[1] = adj (unused by the reference forward)
    const float* W = (const float*)d_in[2];
    const float* A = (const float*)d_in[3];
    float* out = (float*)d_out;

    k_gemm_xwT<<<dim3(N_NODES / 64, F_OUT / 64), 256>>>(x, W);
    k_gemm_hA<<<dim3(N_NODES / 64, HEADS), 256>>>(A);
    k_attn<<<dim3(N_NODES / QTILE, HEADS, NSPLIT), 128>>>();
    k_combine<<<(N_NODES * F_OUT) / (256 * 4), 256>>>(out);
}

// round 10
// speedup vs baseline: 1.4159x; 1.4159x over previous
#include <cuda_runtime.h>
#include <cuda_fp16.h>
#include <math.h>
#include <stdint.h>

#define N_NODES 4096
#define F_IN    256
#define F_OUT   512
#define HEADS   8
#define DH      64
#define LOG2E   1.4426950408889634f

#define KTILE   64
#define NT      (N_NODES / KTILE)   // 64 key tiles
#define QTILE   128                 // q rows per block (32 per warp)
#define PITCH   144                 // bytes per 64-fp16 row (16B aligned, conflict-free)
#define STG     (KTILE * PITCH)     // 9216 bytes per array
#define STAGE_SZ (2 * STG)          // Kh + Kl per stage (18432)

// ---------------- device scratch (no allocs allowed) ----------------
__device__ __align__(256) float  g_h [N_NODES * F_OUT];
__device__ __align__(256) __half g_hh[N_NODES * F_OUT];   // fp16(h)      (K hi == V)
__device__ __align__(256) __half g_hl[N_NODES * F_OUT];   // fp16 residual of h
__device__ __align__(256) __half g_qh[N_NODES * F_OUT];   // fp16(q*log2e)
__device__ __align__(256) __half g_ql[N_NODES * F_OUT];   // fp16 residual

// ---------------- helpers ----------------
__device__ __forceinline__ uint32_t smem_u32(const void* p) {
    uint32_t a;
    asm("{ .reg .u64 t; cvta.to.shared.u64 t, %1; cvt.u32.u64 %0, t; }" : "=r"(a) : "l"(p));
    return a;
}
// pack two fp32 -> fp16x2 (a in low half, b in high half)
__device__ __forceinline__ uint32_t hfpk(float a, float b) {
    uint32_t r; asm("cvt.rn.f16x2.f32 %0, %1, %2;" : "=r"(r) : "f"(b), "f"(a)); return r;
}
// FFMA-pipe exp2 (no MUFU)
__device__ __forceinline__ float exp2_fast(float x) {
    const float MAGIC = 12582912.0f;        // 1.5 * 2^23
    float fn = x + MAGIC;
    int   n  = __float_as_int(fn);
    float t  = fn - MAGIC;
    float f  = x - t;                       // [-0.5, 0.5]
    float p  = 0.0013333558f;
    p = fmaf(p, f, 0.0096181291f);
    p = fmaf(p, f, 0.0555041087f);
    p = fmaf(p, f, 0.2402265070f);
    p = fmaf(p, f, 0.6931471806f);
    p = fmaf(p, f, 1.0f);
    return __int_as_float(__float_as_int(p) + (n << 23));
}
__device__ __forceinline__ void cpa16(uint32_t dst, const void* src) {
    asm volatile("cp.async.cg.shared.global [%0], [%1], 16;" :: "r"(dst), "l"(src) : "memory");
}
#define CP_COMMIT() asm volatile("cp.async.commit_group;" ::: "memory")
#define CP_WAIT0()  asm volatile("cp.async.wait_group 0;" ::: "memory")

__device__ __forceinline__ void ldsm4(uint32_t a, uint32_t& r0, uint32_t& r1,
                                      uint32_t& r2, uint32_t& r3) {
    asm volatile("ldmatrix.sync.aligned.m8n8.x4.shared.b16 {%0,%1,%2,%3}, [%4];"
                 : "=r"(r0), "=r"(r1), "=r"(r2), "=r"(r3) : "r"(a));
}
__device__ __forceinline__ void ldsm4t(uint32_t a, uint32_t& r0, uint32_t& r1,
                                       uint32_t& r2, uint32_t& r3) {
    asm volatile("ldmatrix.sync.aligned.m8n8.x4.trans.shared.b16 {%0,%1,%2,%3}, [%4];"
                 : "=r"(r0), "=r"(r1), "=r"(r2), "=r"(r3) : "r"(a));
}
// D += A(16x16 fp16) * B(16x8 fp16), fp32 accum
__device__ __forceinline__ void mma16816(float* c, const uint32_t* a, uint32_t b0, uint32_t b1) {
    asm volatile(
        "mma.sync.aligned.m16n8k16.row.col.f32.f16.f16.f32 "
        "{%0,%1,%2,%3}, {%4,%5,%6,%7}, {%8,%9}, {%0,%1,%2,%3};"
        : "+f"(c[0]), "+f"(c[1]), "+f"(c[2]), "+f"(c[3])
        : "r"(a[0]), "r"(a[1]), "r"(a[2]), "r"(a[3]), "r"(b0), "r"(b1));
}

// ---------------------------------------------------------------------------
// Kernel 1: h = x @ W^T, fp32; epilogue also writes fp16 hi/lo split.
// ---------------------------------------------------------------------------
__global__ __launch_bounds__(256) void k_gemm_xwT(const float* __restrict__ X,
                                                  const float* __restrict__ W) {
    __shared__ float sX[16][68];
    __shared__ float sW[16][68];
    const int tid = threadIdx.x;
    const int ty = tid >> 4, tx = tid & 15;
    const int m0 = blockIdx.x * 64, n0 = blockIdx.y * 64;

    float acc[4][4] = {};
    for (int k0 = 0; k0 < F_IN; k0 += 16) {
        {
            const int r  = tid >> 2;
            const int kk = (tid & 3) * 4;
            float4 v = *(const float4*)&X[(m0 + r) * F_IN + k0 + kk];
            sX[kk + 0][r] = v.x; sX[kk + 1][r] = v.y;
            sX[kk + 2][r] = v.z; sX[kk + 3][r] = v.w;
            float4 w = *(const float4*)&W[(n0 + r) * F_IN + k0 + kk];
            sW[kk + 0][r] = w.x; sW[kk + 1][r] = w.y;
            sW[kk + 2][r] = w.z; sW[kk + 3][r] = w.w;
        }
        __syncthreads();
        #pragma unroll
        for (int kk = 0; kk < 16; kk++) {
            float a[4], b[4];
            #pragma unroll
            for (int i = 0; i < 4; i++) a[i] = sX[kk][ty * 4 + i];
            #pragma unroll
            for (int j = 0; j < 4; j++) b[j] = sW[kk][tx * 4 + j];
            #pragma unroll
            for (int i = 0; i < 4; i++)
                #pragma unroll
                for (int j = 0; j < 4; j++)
                    acc[i][j] = fmaf(a[i], b[j], acc[i][j]);
        }
        __syncthreads();
    }
    #pragma unroll
    for (int i = 0; i < 4; i++) {
        const int idx = (m0 + ty * 4 + i) * F_OUT + n0 + tx * 4;
        *(float4*)&g_h[idx] = make_float4(acc[i][0], acc[i][1], acc[i][2], acc[i][3]);
        #pragma unroll
        for (int jp = 0; jp < 2; jp++) {
            float v0 = acc[i][2 * jp], v1 = acc[i][2 * jp + 1];
            uint32_t hp = hfpk(v0, v1);
            __half2 h2 = *(__half2*)&hp;
            float r0 = v0 - __low2float(h2);
            float r1 = v1 - __high2float(h2);
            *(uint32_t*)&g_hh[idx + 2 * jp] = hp;
            *(uint32_t*)&g_hl[idx + 2 * jp] = hfpk(r0, r1);
        }
    }
}

// ---------------------------------------------------------------------------
// Kernel 2: q = h @ A (per head), scaled by log2(e), written as fp16 hi/lo.
// ---------------------------------------------------------------------------
__global__ __launch_bounds__(256) void k_gemm_hA(const float* __restrict__ A) {
    __shared__ float sH[64][65];
    __shared__ float sA[64][65];
    const int tid = threadIdx.x;
    const int ty = tid >> 4, tx = tid & 15;
    const int head = blockIdx.y;
    const int n0 = blockIdx.x * 64;

    {
        const int r  = tid >> 2;
        const int c0 = (tid & 3) * 16;
        #pragma unroll
        for (int cc = 0; cc < 16; cc += 4) {
            float4 v = *(const float4*)&g_h[(n0 + r) * F_OUT + head * DH + c0 + cc];
            sH[c0 + cc + 0][r] = v.x; sH[c0 + cc + 1][r] = v.y;
            sH[c0 + cc + 2][r] = v.z; sH[c0 + cc + 3][r] = v.w;
            float4 a = *(const float4*)&A[head * DH * DH + r * DH + c0 + cc];
            sA[r][c0 + cc + 0] = a.x; sA[r][c0 + cc + 1] = a.y;
            sA[r][c0 + cc + 2] = a.z; sA[r][c0 + cc + 3] = a.w;
        }
    }
    __syncthreads();

    float acc[4][4] = {};
    #pragma unroll 16
    for (int d = 0; d < DH; d++) {
        float a[4], b[4];
        #pragma unroll
        for (int i = 0; i < 4; i++) a[i] = sH[d][ty * 4 + i];
        #pragma unroll
        for (int j = 0; j < 4; j++) b[j] = sA[d][tx * 4 + j];
        #pragma unroll
        for (int i = 0; i < 4; i++)
            #pragma unroll
            for (int j = 0; j < 4; j++)
                acc[i][j] = fmaf(a[i], b[j], acc[i][j]);
    }
    #pragma unroll
    for (int i = 0; i < 4; i++) {
        const int idx = (n0 + ty * 4 + i) * F_OUT + head * DH + tx * 4;
        #pragma unroll
        for (int jp = 0; jp < 2; jp++) {
            float v0 = acc[i][2 * jp] * LOG2E, v1 = acc[i][2 * jp + 1] * LOG2E;
            uint32_t hp = hfpk(v0, v1);
            __half2 h2 = *(__half2*)&hp;
            float r0 = v0 - __low2float(h2);
            float r1 = v1 - __high2float(h2);
            *(uint32_t*)&g_qh[idx + 2 * jp] = hp;
            *(uint32_t*)&g_ql[idx + 2 * jp] = hfpk(r0, r1);
        }
    }
}

// ---------------------------------------------------------------------------
// Kernel 3: flash attention via fp16 mma.sync.
// S: 3-mma compensated (Qh*Kh + Ql*Kh + Qh*Kl), ~21-bit effective.
// PV: SINGLE mma (P fp16, V = Kh fp16); P scaled by 2^-6 (cancels in O/l).
// Warp owns 32 q rows (2 m16 tiles per B-fragment). Grid 256, 2 blocks/SM.
// ---------------------------------------------------------------------------
__global__ __launch_bounds__(128, 2) void k_attn(float* __restrict__ Out) {
    __shared__ __align__(16) char smem[2 * STAGE_SZ];   // 36864 B (also Q staging)
    const uint32_t sb = smem_u32(smem);

    const int tid  = threadIdx.x;
    const int w    = tid >> 5;
    const int lane = tid & 31;
    const int head = blockIdx.y;
    const int q0   = blockIdx.x * QTILE;
    const int hb   = head * DH;

    // ldmatrix per-lane address constants
    const int lm = lane >> 3, lr = lane & 7;
    const int sKey = ((lm >> 1) << 3) + lr;   // S-B: key row offset
    const int sD   = (lm & 1) << 3;           // S-B: d col offset
    const int vKey = ((lm & 1) << 3) + lr;    // V-B(trans): key row offset
    const int vD   = (lm >> 1) << 3;          // V-B(trans): dim col offset
    const int qRow = ((lm & 1) << 3) + lr;    // Q-A: row offset within 16-row tile
    const int qCol = (lm >> 1) << 3;

    // ---- stage Q (hi at sb, lo at sb+STAGE_SZ) in the K-stage area ----
    {
        const int r = tid;                     // 0..127 -> q row
        const __half* qh = &g_qh[(size_t)(q0 + r) * F_OUT + hb];
        const __half* ql = &g_ql[(size_t)(q0 + r) * F_OUT + hb];
        const uint32_t d0 = sb + r * PITCH;
        #pragma unroll
        for (int c = 0; c < 8; c++) cpa16(d0 + c * 16, qh + c * 8);
        const uint32_t d1 = sb + STAGE_SZ + r * PITCH;
        #pragma unroll
        for (int c = 0; c < 8; c++) cpa16(d1 + c * 16, ql + c * 8);
    }
    CP_COMMIT();
    CP_WAIT0();
    __syncthreads();

    // Q A-fragments: [s*2+m] for k-step s (0..3), m-tile m (0..1); hi and lo
    uint32_t qa[8][4], qb[8][4];
    #pragma unroll
    for (int m = 0; m < 2; m++) {
        const uint32_t qbh = sb + (w * 32 + m * 16 + qRow) * PITCH + qCol * 2;
        const uint32_t qbl = qbh + STAGE_SZ;
        #pragma unroll
        for (int s = 0; s < 4; s++) {
            ldsm4(qbh + 16 * s * 2, qa[s * 2 + m][0], qa[s * 2 + m][1],
                                    qa[s * 2 + m][2], qa[s * 2 + m][3]);
            ldsm4(qbl + 16 * s * 2, qb[s * 2 + m][0], qb[s * 2 + m][1],
                                    qb[s * 2 + m][2], qb[s * 2 + m][3]);
        }
    }
    __syncthreads();   // Q staging area now free for K tiles

    // ---- prologue: load K tile 0 into stage 0 ----
    {
        const int r = tid >> 1, cb = (tid & 1) * 4;
        const uint32_t d0 = sb + r * PITCH + cb * 16;
        const __half* kh = &g_hh[(size_t)r * F_OUT + hb];
        const __half* kl = &g_hl[(size_t)r * F_OUT + hb];
        #pragma unroll
        for (int c = 0; c < 4; c++) cpa16(d0 + c * 16, kh + (cb + c) * 8);
        #pragma unroll
        for (int c = 0; c < 4; c++) cpa16(d0 + STG + c * 16, kl + (cb + c) * 8);
    }
    CP_COMMIT();

    float oc[2][8][4];
    #pragma unroll
    for (int m = 0; m < 2; m++)
        #pragma unroll
        for (int j = 0; j < 8; j++)
            #pragma unroll
            for (int k = 0; k < 4; k++) oc[m][j][k] = 0.f;
    float lsum[2][2] = {};   // [m][half]: rows g / g+8

    for (int t = 0; t < NT; t++) {
        CP_WAIT0();
        __syncthreads();
        const uint32_t stg = sb + (t & 1) * STAGE_SZ;

        // prefetch next tile into other stage
        if (t + 1 < NT) {
            const int r = tid >> 1, cb = (tid & 1) * 4;
            const uint32_t d0 = sb + ((t + 1) & 1) * STAGE_SZ + r * PITCH + cb * 16;
            const __half* kh = &g_hh[(size_t)((t + 1) * KTILE + r) * F_OUT + hb];
            const __half* kl = &g_hl[(size_t)((t + 1) * KTILE + r) * F_OUT + hb];
            #pragma unroll
            for (int c = 0; c < 4; c++) cpa16(d0 + c * 16, kh + (cb + c) * 8);
            #pragma unroll
            for (int c = 0; c < 4; c++) cpa16(d0 + STG + c * 16, kl + (cb + c) * 8);
        }
        CP_COMMIT();

        const uint32_t sAddr = stg + sKey * PITCH + sD * 2;
        const uint32_t vAddr = stg + vKey * PITCH + vD * 2;

        // ---- per-16-key block: S -> softmax -> PV ----
        #pragma unroll
        for (int u = 0; u < 4; u++) {
            // S = Q K^T (3-mma compensated), both m-tiles per B-fragment
            float sc[2][2][4];
            #pragma unroll
            for (int m = 0; m < 2; m++)
                #pragma unroll
                for (int k = 0; k < 4; k++) { sc[m][0][k] = 0.f; sc[m][1][k] = 0.f; }

            #pragma unroll
            for (int s = 0; s < 4; s++) {
                const uint32_t a = sAddr + (16 * u) * PITCH + (16 * s) * 2;
                uint32_t h0, h1, h2, h3, l0, l1, l2, l3;
                ldsm4(a,       h0, h1, h2, h3);
                ldsm4(a + STG, l0, l1, l2, l3);
                #pragma unroll
                for (int m = 0; m < 2; m++) {
                    mma16816(sc[m][0], qa[s * 2 + m], h0, h1);
                    mma16816(sc[m][1], qa[s * 2 + m], h2, h3);
                    mma16816(sc[m][0], qa[s * 2 + m], l0, l1);
                    mma16816(sc[m][1], qa[s * 2 + m], l2, l3);
                    mma16816(sc[m][0], qb[s * 2 + m], h0, h1);
                    mma16816(sc[m][1], qb[s * 2 + m], h2, h3);
                }
            }

            // softmax: p = 2^(leaky(s) - 6); single fp16 P A-fragment
            uint32_t pa[2][4];
            #pragma unroll
            for (int m = 0; m < 2; m++) {
                float e[8];
                #pragma unroll
                for (int k = 0; k < 4; k++) {
                    float v0 = sc[m][0][k];
                    e[k] = exp2_fast(fmaxf(v0, 0.2f * v0) - 6.0f);
                    float v1 = sc[m][1][k];
                    e[4 + k] = exp2_fast(fmaxf(v1, 0.2f * v1) - 6.0f);
                }
                lsum[m][0] += (e[0] + e[1]) + (e[4] + e[5]);
                lsum[m][1] += (e[2] + e[3]) + (e[6] + e[7]);

                pa[m][0] = hfpk(e[0], e[1]);
                pa[m][1] = hfpk(e[2], e[3]);
                pa[m][2] = hfpk(e[4], e[5]);
                pa[m][3] = hfpk(e[6], e[7]);
            }

            // O += P V (V = Kh tile, trans ldmatrix), single mma per n-half per m
            #pragma unroll
            for (int d = 0; d < 4; d++) {
                const uint32_t a = vAddr + (16 * u) * PITCH + (16 * d) * 2;
                uint32_t h0, h1, h2, h3;
                ldsm4t(a, h0, h1, h2, h3);
                #pragma unroll
                for (int m = 0; m < 2; m++) {
                    mma16816(oc[m][2 * d],     pa[m], h0, h1);
                    mma16816(oc[m][2 * d + 1], pa[m], h2, h3);
                }
            }
        }
    }

    // ---- reduce lsum across quad, normalize, write O ----
    const int g  = lane >> 2, tg = lane & 3;
    #pragma unroll
    for (int m = 0; m < 2; m++) {
        float lA = lsum[m][0], lB = lsum[m][1];
        lA += __shfl_xor_sync(0xffffffffu, lA, 1);
        lA += __shfl_xor_sync(0xffffffffu, lA, 2);
        lB += __shfl_xor_sync(0xffffffffu, lB, 1);
        lB += __shfl_xor_sync(0xffffffffu, lB, 2);
        const float invA = 1.0f / lA, invB = 1.0f / lB;

        const int rowA = q0 + w * 32 + m * 16 + g;
        float* outA = &Out[(size_t)rowA * F_OUT + hb + 2 * tg];
        float* outB = outA + 8 * F_OUT;
        #pragma unroll
        for (int j = 0; j < 8; j++) {
            *(float2*)(outA + 8 * j) = make_float2(oc[m][j][0] * invA, oc[m][j][1] * invA);
            *(float2*)(outB + 8 * j) = make_float2(oc[m][j][2] * invB, oc[m][j][3] * invB);
        }
    }
}

// ---------------------------------------------------------------------------
extern "C" void kernel_launch(void* const* d_in, const int* in_sizes, int n_in,
                              void* d_out, int out_size) {
    const float* x = (const float*)d_in[0];
    // d_in[1] = adj (unused by the reference forward)
    const float* W = (const float*)d_in[2];
    const float* A = (const float*)d_in[3];
    float* out = (float*)d_out;

    k_gemm_xwT<<<dim3(N_NODES / 64, F_OUT / 64), 256>>>(x, W);
    k_gemm_hA<<<dim3(N_NODES / 64, HEADS), 256>>>(A);
    k_attn<<<dim3(N_NODES / QTILE, HEADS), 128>>>(out);
}

// round 11
// speedup vs baseline: 2.0888x; 1.4753x over previous
#include <cuda_runtime.h>
#include <cuda_fp16.h>
#include <math.h>
#include <stdint.h>

#define N_NODES 4096
#define F_IN    256
#define F_OUT   512
#define HEADS   8
#define DH      64
#define LOG2E   1.4426950408889634f

#define KTILE   64
#define NT      (N_NODES / KTILE)   // 64 key tiles
#define QTILE   128                 // q rows per block (32 per warp)
#define PITCH   144                 // bytes per 64-fp16 row (16B aligned, conflict-free)
#define STG     (KTILE * PITCH)     // 9216 bytes per stage
#define SMEM_SZ (2 * STG)           // 18432 (double-buffered K; also fits 128-row Q staging)

// ---------------- device scratch (no allocs allowed) ----------------
__device__ __align__(256) float  g_h [N_NODES * F_OUT];
__device__ __align__(256) __half g_hh[N_NODES * F_OUT];   // fp16(h)  (K == V)
__device__ __align__(256) __half g_qh[N_NODES * F_OUT];   // fp16(q * log2e)

// ---------------- helpers ----------------
__device__ __forceinline__ uint32_t smem_u32(const void* p) {
    uint32_t a;
    asm("{ .reg .u64 t; cvta.to.shared.u64 t, %1; cvt.u32.u64 %0, t; }" : "=r"(a) : "l"(p));
    return a;
}
// pack two fp32 -> fp16x2 (a in low half, b in high half)
__device__ __forceinline__ uint32_t hfpk(float a, float b) {
    uint32_t r; asm("cvt.rn.f16x2.f32 %0, %1, %2;" : "=r"(r) : "f"(b), "f"(a)); return r;
}
// FFMA-pipe exp2 (no MUFU)
__device__ __forceinline__ float exp2_fast(float x) {
    const float MAGIC = 12582912.0f;        // 1.5 * 2^23
    float fn = x + MAGIC;
    int   n  = __float_as_int(fn);
    float t  = fn - MAGIC;
    float f  = x - t;                       // [-0.5, 0.5]
    float p  = 0.0013333558f;
    p = fmaf(p, f, 0.0096181291f);
    p = fmaf(p, f, 0.0555041087f);
    p = fmaf(p, f, 0.2402265070f);
    p = fmaf(p, f, 0.6931471806f);
    p = fmaf(p, f, 1.0f);
    return __int_as_float(__float_as_int(p) + (n << 23));
}
__device__ __forceinline__ void cpa16(uint32_t dst, const void* src) {
    asm volatile("cp.async.cg.shared.global [%0], [%1], 16;" :: "r"(dst), "l"(src) : "memory");
}
#define CP_COMMIT() asm volatile("cp.async.commit_group;" ::: "memory")
#define CP_WAIT0()  asm volatile("cp.async.wait_group 0;" ::: "memory")

__device__ __forceinline__ void ldsm4(uint32_t a, uint32_t& r0, uint32_t& r1,
                                      uint32_t& r2, uint32_t& r3) {
    asm volatile("ldmatrix.sync.aligned.m8n8.x4.shared.b16 {%0,%1,%2,%3}, [%4];"
                 : "=r"(r0), "=r"(r1), "=r"(r2), "=r"(r3) : "r"(a));
}
__device__ __forceinline__ void ldsm4t(uint32_t a, uint32_t& r0, uint32_t& r1,
                                       uint32_t& r2, uint32_t& r3) {
    asm volatile("ldmatrix.sync.aligned.m8n8.x4.trans.shared.b16 {%0,%1,%2,%3}, [%4];"
                 : "=r"(r0), "=r"(r1), "=r"(r2), "=r"(r3) : "r"(a));
}
// D += A(16x16 fp16) * B(16x8 fp16), fp32 accum
__device__ __forceinline__ void mma16816(float* c, const uint32_t* a, uint32_t b0, uint32_t b1) {
    asm volatile(
        "mma.sync.aligned.m16n8k16.row.col.f32.f16.f16.f32 "
        "{%0,%1,%2,%3}, {%4,%5,%6,%7}, {%8,%9}, {%0,%1,%2,%3};"
        : "+f"(c[0]), "+f"(c[1]), "+f"(c[2]), "+f"(c[3])
        : "r"(a[0]), "r"(a[1]), "r"(a[2]), "r"(a[3]), "r"(b0), "r"(b1));
}

// ---------------------------------------------------------------------------
// Kernel 1: h = x @ W^T, fp32; epilogue also writes fp16(h).
// ---------------------------------------------------------------------------
__global__ __launch_bounds__(256) void k_gemm_xwT(const float* __restrict__ X,
                                                  const float* __restrict__ W) {
    __shared__ float sX[16][68];
    __shared__ float sW[16][68];
    const int tid = threadIdx.x;
    const int ty = tid >> 4, tx = tid & 15;
    const int m0 = blockIdx.x * 64, n0 = blockIdx.y * 64;

    float acc[4][4] = {};
    for (int k0 = 0; k0 < F_IN; k0 += 16) {
        {
            const int r  = tid >> 2;
            const int kk = (tid & 3) * 4;
            float4 v = *(const float4*)&X[(m0 + r) * F_IN + k0 + kk];
            sX[kk + 0][r] = v.x; sX[kk + 1][r] = v.y;
            sX[kk + 2][r] = v.z; sX[kk + 3][r] = v.w;
            float4 w = *(const float4*)&W[(n0 + r) * F_IN + k0 + kk];
            sW[kk + 0][r] = w.x; sW[kk + 1][r] = w.y;
            sW[kk + 2][r] = w.z; sW[kk + 3][r] = w.w;
        }
        __syncthreads();
        #pragma unroll
        for (int kk = 0; kk < 16; kk++) {
            float a[4], b[4];
            #pragma unroll
            for (int i = 0; i < 4; i++) a[i] = sX[kk][ty * 4 + i];
            #pragma unroll
            for (int j = 0; j < 4; j++) b[j] = sW[kk][tx * 4 + j];
            #pragma unroll
            for (int i = 0; i < 4; i++)
                #pragma unroll
                for (int j = 0; j < 4; j++)
                    acc[i][j] = fmaf(a[i], b[j], acc[i][j]);
        }
        __syncthreads();
    }
    #pragma unroll
    for (int i = 0; i < 4; i++) {
        const int idx = (m0 + ty * 4 + i) * F_OUT + n0 + tx * 4;
        *(float4*)&g_h[idx] = make_float4(acc[i][0], acc[i][1], acc[i][2], acc[i][3]);
        *(uint32_t*)&g_hh[idx]     = hfpk(acc[i][0], acc[i][1]);
        *(uint32_t*)&g_hh[idx + 2] = hfpk(acc[i][2], acc[i][3]);
    }
}

// ---------------------------------------------------------------------------
// Kernel 2: q = h @ A (per head), scaled by log2(e), written as fp16.
// ---------------------------------------------------------------------------
__global__ __launch_bounds__(256) void k_gemm_hA(const float* __restrict__ A) {
    __shared__ float sH[64][65];
    __shared__ float sA[64][65];
    const int tid = threadIdx.x;
    const int ty = tid >> 4, tx = tid & 15;
    const int head = blockIdx.y;
    const int n0 = blockIdx.x * 64;

    {
        const int r  = tid >> 2;
        const int c0 = (tid & 3) * 16;
        #pragma unroll
        for (int cc = 0; cc < 16; cc += 4) {
            float4 v = *(const float4*)&g_h[(n0 + r) * F_OUT + head * DH + c0 + cc];
            sH[c0 + cc + 0][r] = v.x; sH[c0 + cc + 1][r] = v.y;
            sH[c0 + cc + 2][r] = v.z; sH[c0 + cc + 3][r] = v.w;
            float4 a = *(const float4*)&A[head * DH * DH + r * DH + c0 + cc];
            sA[r][c0 + cc + 0] = a.x; sA[r][c0 + cc + 1] = a.y;
            sA[r][c0 + cc + 2] = a.z; sA[r][c0 + cc + 3] = a.w;
        }
    }
    __syncthreads();

    float acc[4][4] = {};
    #pragma unroll 16
    for (int d = 0; d < DH; d++) {
        float a[4], b[4];
        #pragma unroll
        for (int i = 0; i < 4; i++) a[i] = sH[d][ty * 4 + i];
        #pragma unroll
        for (int j = 0; j < 4; j++) b[j] = sA[d][tx * 4 + j];
        #pragma unroll
        for (int i = 0; i < 4; i++)
            #pragma unroll
            for (int j = 0; j < 4; j++)
                acc[i][j] = fmaf(a[i], b[j], acc[i][j]);
    }
    #pragma unroll
    for (int i = 0; i < 4; i++) {
        const int idx = (n0 + ty * 4 + i) * F_OUT + head * DH + tx * 4;
        *(uint32_t*)&g_qh[idx]     = hfpk(acc[i][0] * LOG2E, acc[i][1] * LOG2E);
        *(uint32_t*)&g_qh[idx + 2] = hfpk(acc[i][2] * LOG2E, acc[i][3] * LOG2E);
    }
}

// ---------------------------------------------------------------------------
// Kernel 3: pure-fp16 flash attention via mma.sync (fp32 accumulate).
// S: 1 mma per n-half (Qh * Kh). PV: 1 mma per n-half (P * Vh), P scaled 2^-6.
// Warp owns 32 q rows (2 m16 tiles per B-fragment). Grid 256.
// ---------------------------------------------------------------------------
__global__ __launch_bounds__(128, 2) void k_attn(float* __restrict__ Out) {
    __shared__ __align__(16) char smem[SMEM_SZ];   // 18432 B (K stages; Q staging)
    const uint32_t sb = smem_u32(smem);

    const int tid  = threadIdx.x;
    const int w    = tid >> 5;
    const int lane = tid & 31;
    const int head = blockIdx.y;
    const int q0   = blockIdx.x * QTILE;
    const int hb   = head * DH;

    // ldmatrix per-lane address constants
    const int lm = lane >> 3, lr = lane & 7;
    const int sKey = ((lm >> 1) << 3) + lr;   // S-B: key row offset
    const int sD   = (lm & 1) << 3;           // S-B: d col offset
    const int vKey = ((lm & 1) << 3) + lr;    // V-B(trans): key row offset
    const int vD   = (lm >> 1) << 3;          // V-B(trans): dim col offset
    const int qRow = ((lm & 1) << 3) + lr;    // Q-A: row offset within 16-row tile
    const int qCol = (lm >> 1) << 3;

    // ---- stage Q (128 rows x 144B = exactly the 2-stage area) ----
    {
        const int r = tid;                     // 0..127 -> q row
        const __half* qh = &g_qh[(size_t)(q0 + r) * F_OUT + hb];
        const uint32_t d0 = sb + r * PITCH;
        #pragma unroll
        for (int c = 0; c < 8; c++) cpa16(d0 + c * 16, qh + c * 8);
    }
    CP_COMMIT();
    CP_WAIT0();
    __syncthreads();

    // Q A-fragments: [s*2+m] for k-step s (0..3), m-tile m (0..1)
    uint32_t qa[8][4];
    #pragma unroll
    for (int m = 0; m < 2; m++) {
        const uint32_t qb = sb + (w * 32 + m * 16 + qRow) * PITCH + qCol * 2;
        #pragma unroll
        for (int s = 0; s < 4; s++)
            ldsm4(qb + 16 * s * 2, qa[s * 2 + m][0], qa[s * 2 + m][1],
                                   qa[s * 2 + m][2], qa[s * 2 + m][3]);
    }
    __syncthreads();   // Q staging area now free for K tiles

    // ---- prologue: load K tile 0 into stage 0 ----
    {
        const int r = tid >> 1, cb = (tid & 1) * 4;
        const uint32_t d0 = sb + r * PITCH + cb * 16;
        const __half* kh = &g_hh[(size_t)r * F_OUT + hb];
        #pragma unroll
        for (int c = 0; c < 4; c++) cpa16(d0 + c * 16, kh + (cb + c) * 8);
    }
    CP_COMMIT();

    float oc[2][8][4];
    #pragma unroll
    for (int m = 0; m < 2; m++)
        #pragma unroll
        for (int j = 0; j < 8; j++)
            #pragma unroll
            for (int k = 0; k < 4; k++) oc[m][j][k] = 0.f;
    float lsum[2][2] = {};   // [m][half]: rows g / g+8

    for (int t = 0; t < NT; t++) {
        CP_WAIT0();
        __syncthreads();
        const uint32_t stg = sb + (t & 1) * STG;

        // prefetch next tile into other stage
        if (t + 1 < NT) {
            const int r = tid >> 1, cb = (tid & 1) * 4;
            const uint32_t d0 = sb + ((t + 1) & 1) * STG + r * PITCH + cb * 16;
            const __half* kh = &g_hh[(size_t)((t + 1) * KTILE + r) * F_OUT + hb];
            #pragma unroll
            for (int c = 0; c < 4; c++) cpa16(d0 + c * 16, kh + (cb + c) * 8);
        }
        CP_COMMIT();

        const uint32_t sAddr = stg + sKey * PITCH + sD * 2;
        const uint32_t vAddr = stg + vKey * PITCH + vD * 2;

        // ---- per-16-key block: S -> softmax -> PV ----
        #pragma unroll
        for (int u = 0; u < 4; u++) {
            // S = Q K^T, both m-tiles per B-fragment
            float sc[2][2][4];
            #pragma unroll
            for (int m = 0; m < 2; m++)
                #pragma unroll
                for (int k = 0; k < 4; k++) { sc[m][0][k] = 0.f; sc[m][1][k] = 0.f; }

            #pragma unroll
            for (int s = 0; s < 4; s++) {
                const uint32_t a = sAddr + (16 * u) * PITCH + (16 * s) * 2;
                uint32_t h0, h1, h2, h3;
                ldsm4(a, h0, h1, h2, h3);
                #pragma unroll
                for (int m = 0; m < 2; m++) {
                    mma16816(sc[m][0], qa[s * 2 + m], h0, h1);
                    mma16816(sc[m][1], qa[s * 2 + m], h2, h3);
                }
            }

            // softmax: p = 2^(leaky(s) - 6); fp16 P A-fragment
            uint32_t pa[2][4];
            #pragma unroll
            for (int m = 0; m < 2; m++) {
                float e[8];
                #pragma unroll
                for (int k = 0; k < 4; k++) {
                    float v0 = sc[m][0][k];
                    e[k] = exp2_fast(fmaxf(v0, 0.2f * v0) - 6.0f);
                    float v1 = sc[m][1][k];
                    e[4 + k] = exp2_fast(fmaxf(v1, 0.2f * v1) - 6.0f);
                }
                lsum[m][0] += (e[0] + e[1]) + (e[4] + e[5]);
                lsum[m][1] += (e[2] + e[3]) + (e[6] + e[7]);

                pa[m][0] = hfpk(e[0], e[1]);
                pa[m][1] = hfpk(e[2], e[3]);
                pa[m][2] = hfpk(e[4], e[5]);
                pa[m][3] = hfpk(e[6], e[7]);
            }

            // O += P V (V = K tile, trans ldmatrix), both m-tiles per B-fragment
            #pragma unroll
            for (int d = 0; d < 4; d++) {
                const uint32_t a = vAddr + (16 * u) * PITCH + (16 * d) * 2;
                uint32_t h0, h1, h2, h3;
                ldsm4t(a, h0, h1, h2, h3);
                #pragma unroll
                for (int m = 0; m < 2; m++) {
                    mma16816(oc[m][2 * d],     pa[m], h0, h1);
                    mma16816(oc[m][2 * d + 1], pa[m], h2, h3);
                }
            }
        }
    }

    // ---- reduce lsum across quad, normalize, write O ----
    const int g  = lane >> 2, tg = lane & 3;
    #pragma unroll
    for (int m = 0; m < 2; m++) {
        float lA = lsum[m][0], lB = lsum[m][1];
        lA += __shfl_xor_sync(0xffffffffu, lA, 1);
        lA += __shfl_xor_sync(0xffffffffu, lA, 2);
        lB += __shfl_xor_sync(0xffffffffu, lB, 1);
        lB += __shfl_xor_sync(0xffffffffu, lB, 2);
        const float invA = 1.0f / lA, invB = 1.0f / lB;

        const int rowA = q0 + w * 32 + m * 16 + g;
        float* outA = &Out[(size_t)rowA * F_OUT + hb + 2 * tg];
        float* outB = outA + 8 * F_OUT;
        #pragma unroll
        for (int j = 0; j < 8; j++) {
            *(float2*)(outA + 8 * j) = make_float2(oc[m][j][0] * invA, oc[m][j][1] * invA);
            *(float2*)(outB + 8 * j) = make_float2(oc[m][j][2] * invB, oc[m][j][3] * invB);
        }
    }
}

// ---------------------------------------------------------------------------
extern "C" void kernel_launch(void* const* d_in, const int* in_sizes, int n_in,
                              void* d_out, int out_size) {
    const float* x = (const float*)d_in[0];
    // d_in[1] = adj (unused by the reference forward)
    const float* W = (const float*)d_in[2];
    const float* A = (const float*)d_in[3];
    float* out = (float*)d_out;

    k_gemm_xwT<<<dim3(N_NODES / 64, F_OUT / 64), 256>>>(x, W);
    k_gemm_hA<<<dim3(N_NODES / 64, HEADS), 256>>>(A);
    k_attn<<<dim3(N_NODES / QTILE, HEADS), 128>>>(out);
}

// round 12
// speedup vs baseline: 2.3448x; 1.1226x over previous
#include <cuda_runtime.h>
#include <cuda_fp16.h>
#include <math.h>
#include <stdint.h>

#define N_NODES 4096
#define F_IN    256
#define F_OUT   512
#define HEADS   8
#define DH      64
#define LOG2E   1.4426950408889634f

#define KTILE   64
#define NT      (N_NODES / KTILE)   // 64 key tiles
#define QTILE   128                 // q rows per block (32 per warp)
#define PITCH   144                 // bytes per 64-fp16 row (conflict-free)
#define STG     (KTILE * PITCH)     // 9216 bytes per stage
#define SMEM_SZ (2 * STG)           // 18432

#define N_X (N_NODES * F_IN)
#define N_W (F_OUT * F_IN)
#define N_A (HEADS * DH * DH)

// ---------------- device scratch (no allocs allowed) ----------------
__device__ __align__(256) __half g_xh[N_X], g_xl[N_X];
__device__ __align__(256) __half g_wh[N_W], g_wl[N_W];
__device__ __align__(256) __half g_ah[N_A], g_al[N_A];
__device__ __align__(256) __half g_hh[N_NODES * F_OUT];   // fp16(h)  (K == V)
__device__ __align__(256) __half g_hl[N_NODES * F_OUT];   // fp16 residual of h
__device__ __align__(256) __half g_qh[N_NODES * F_OUT];   // fp16(q * log2e)

// ---------------- helpers ----------------
__device__ __forceinline__ uint32_t smem_u32(const void* p) {
    uint32_t a;
    asm("{ .reg .u64 t; cvta.to.shared.u64 t, %1; cvt.u32.u64 %0, t; }" : "=r"(a) : "l"(p));
    return a;
}
// pack two fp32 -> fp16x2 (a in low half, b in high half)
__device__ __forceinline__ uint32_t hfpk(float a, float b) {
    uint32_t r; asm("cvt.rn.f16x2.f32 %0, %1, %2;" : "=r"(r) : "f"(b), "f"(a)); return r;
}
// FFMA-pipe exp2 (no MUFU)
__device__ __forceinline__ float exp2_fast(float x) {
    const float MAGIC = 12582912.0f;        // 1.5 * 2^23
    float fn = x + MAGIC;
    int   n  = __float_as_int(fn);
    float t  = fn - MAGIC;
    float f  = x - t;                       // [-0.5, 0.5]
    float p  = 0.0013333558f;
    p = fmaf(p, f, 0.0096181291f);
    p = fmaf(p, f, 0.0555041087f);
    p = fmaf(p, f, 0.2402265070f);
    p = fmaf(p, f, 0.6931471806f);
    p = fmaf(p, f, 1.0f);
    return __int_as_float(__float_as_int(p) + (n << 23));
}
__device__ __forceinline__ void cpa16(uint32_t dst, const void* src) {
    asm volatile("cp.async.cg.shared.global [%0], [%1], 16;" :: "r"(dst), "l"(src) : "memory");
}
#define CP_COMMIT() asm volatile("cp.async.commit_group;" ::: "memory")
#define CP_WAIT0()  asm volatile("cp.async.wait_group 0;" ::: "memory")

__device__ __forceinline__ void ldsm4(uint32_t a, uint32_t& r0, uint32_t& r1,
                                      uint32_t& r2, uint32_t& r3) {
    asm volatile("ldmatrix.sync.aligned.m8n8.x4.shared.b16 {%0,%1,%2,%3}, [%4];"
                 : "=r"(r0), "=r"(r1), "=r"(r2), "=r"(r3) : "r"(a));
}
__device__ __forceinline__ void ldsm4t(uint32_t a, uint32_t& r0, uint32_t& r1,
                                       uint32_t& r2, uint32_t& r3) {
    asm volatile("ldmatrix.sync.aligned.m8n8.x4.trans.shared.b16 {%0,%1,%2,%3}, [%4];"
                 : "=r"(r0), "=r"(r1), "=r"(r2), "=r"(r3) : "r"(a));
}
// D += A(16x16 fp16) * B(16x8 fp16), fp32 accum
__device__ __forceinline__ void mma16816(float* c, const uint32_t* a, uint32_t b0, uint32_t b1) {
    asm volatile(
        "mma.sync.aligned.m16n8k16.row.col.f32.f16.f16.f32 "
        "{%0,%1,%2,%3}, {%4,%5,%6,%7}, {%8,%9}, {%0,%1,%2,%3};"
        : "+f"(c[0]), "+f"(c[1]), "+f"(c[2]), "+f"(c[3])
        : "r"(a[0]), "r"(a[1]), "r"(a[2]), "r"(a[3]), "r"(b0), "r"(b1));
}

// ---------------------------------------------------------------------------
// Kernel 0: convert x, W, A to fp16 hi/lo pairs.
// ---------------------------------------------------------------------------
__global__ __launch_bounds__(256) void k_cvt(const float* __restrict__ X,
                                             const float* __restrict__ W,
                                             const float* __restrict__ A) {
    const int i = (blockIdx.x * 256 + threadIdx.x) * 2;   // element index (pairs)
    const float* src; __half *dh, *dl; int off;
    if (i < N_X)            { src = X; dh = g_xh; dl = g_xl; off = i; }
    else if (i < N_X + N_W) { src = W; dh = g_wh; dl = g_wl; off = i - N_X; }
    else                    { src = A; dh = g_ah; dl = g_al; off = i - N_X - N_W; }
    float2 v = *(const float2*)&src[off];
    uint32_t hp = hfpk(v.x, v.y);
    __half2 h2 = *(__half2*)&hp;
    uint32_t lp = hfpk(v.x - __low2float(h2), v.y - __high2float(h2));
    *(uint32_t*)&dh[off] = hp;
    *(uint32_t*)&dl[off] = lp;
}

// ---------------------------------------------------------------------------
// Kernel 1: h = x @ W^T via 3-term compensated fp16 mma (fp32-accurate h).
// Block 128 threads / 4 warps; out tile 128 rows x 64 cols; K chunks of 32.
// Writes g_hh (fp16 hi) + g_hl (fp16 residual).
// ---------------------------------------------------------------------------
#define P80     80
#define MM1_XH  0
#define MM1_XL  10240
#define MM1_WH  20480
#define MM1_WL  25600
#define MM1_SZ  30720

__global__ __launch_bounds__(128) void k_mm1() {
    __shared__ __align__(16) char smem[MM1_SZ];
    const uint32_t sb = smem_u32(smem);
    const int tid = threadIdx.x, w = tid >> 5, lane = tid & 31;
    const int m0 = blockIdx.x * 128, o0 = blockIdx.y * 64;
    const int lm = lane >> 3, lr = lane & 7;
    const int sKey = ((lm >> 1) << 3) + lr;
    const int sD   = (lm & 1) << 3;
    const int qRow = ((lm & 1) << 3) + lr;
    const int qCol = (lm >> 1) << 3;

    float oc[2][8][4] = {};

    for (int kc = 0; kc < F_IN / 32; kc++) {
        const int k0 = kc * 32;
        {
            const __half* xh = &g_xh[(size_t)(m0 + tid) * F_IN + k0];
            const __half* xl = &g_xl[(size_t)(m0 + tid) * F_IN + k0];
            const uint32_t dxh = sb + MM1_XH + tid * P80;
            const uint32_t dxl = sb + MM1_XL + tid * P80;
            #pragma unroll
            for (int c = 0; c < 4; c++) {
                cpa16(dxh + c * 16, xh + c * 8);
                cpa16(dxl + c * 16, xl + c * 8);
            }
            const int r = tid & 63;
            const __half* ws = (tid < 64) ? &g_wh[(size_t)(o0 + r) * F_IN + k0]
                                          : &g_wl[(size_t)(o0 + r) * F_IN + k0];
            const uint32_t dw = sb + ((tid < 64) ? MM1_WH : MM1_WL) + r * P80;
            #pragma unroll
            for (int c = 0; c < 4; c++) cpa16(dw + c * 16, ws + c * 8);
        }
        CP_COMMIT(); CP_WAIT0(); __syncthreads();

        uint32_t ah[4][4], al[4][4];   // [s*2+m]
        #pragma unroll
        for (int m = 0; m < 2; m++) {
            const uint32_t bh = sb + MM1_XH + (w * 32 + m * 16 + qRow) * P80 + qCol * 2;
            const uint32_t bl = sb + MM1_XL + (w * 32 + m * 16 + qRow) * P80 + qCol * 2;
            #pragma unroll
            for (int s = 0; s < 2; s++) {
                ldsm4(bh + s * 32, ah[s * 2 + m][0], ah[s * 2 + m][1],
                                   ah[s * 2 + m][2], ah[s * 2 + m][3]);
                ldsm4(bl + s * 32, al[s * 2 + m][0], al[s * 2 + m][1],
                                   al[s * 2 + m][2], al[s * 2 + m][3]);
            }
        }
        #pragma unroll
        for (int s = 0; s < 2; s++) {
            #pragma unroll
            for (int u = 0; u < 4; u++) {
                uint32_t bh0, bh1, bh2, bh3, bl0, bl1, bl2, bl3;
                ldsm4(sb + MM1_WH + (u * 16 + sKey) * P80 + s * 32 + sD * 2, bh0, bh1, bh2, bh3);
                ldsm4(sb + MM1_WL + (u * 16 + sKey) * P80 + s * 32 + sD * 2, bl0, bl1, bl2, bl3);
                #pragma unroll
                for (int m = 0; m < 2; m++) {
                    mma16816(oc[m][2 * u],     ah[s * 2 + m], bh0, bh1);
                    mma16816(oc[m][2 * u],     al[s * 2 + m], bh0, bh1);
                    mma16816(oc[m][2 * u],     ah[s * 2 + m], bl0, bl1);
                    mma16816(oc[m][2 * u + 1], ah[s * 2 + m], bh2, bh3);
                    mma16816(oc[m][2 * u + 1], al[s * 2 + m], bh2, bh3);
                    mma16816(oc[m][2 * u + 1], ah[s * 2 + m], bl2, bl3);
                }
            }
        }
        __syncthreads();
    }

    const int g = lane >> 2, tg = lane & 3;
    #pragma unroll
    for (int m = 0; m < 2; m++) {
        const int rowA = m0 + w * 32 + m * 16 + g;
        #pragma unroll
        for (int j = 0; j < 8; j++) {
            const int col = o0 + j * 8 + 2 * tg;
            float a0 = oc[m][j][0], a1 = oc[m][j][1];
            uint32_t hp = hfpk(a0, a1);
            __half2 h2 = *(__half2*)&hp;
            *(uint32_t*)&g_hh[(size_t)rowA * F_OUT + col] = hp;
            *(uint32_t*)&g_hl[(size_t)rowA * F_OUT + col] =
                hfpk(a0 - __low2float(h2), a1 - __high2float(h2));
            float b0 = oc[m][j][2], b1 = oc[m][j][3];
            uint32_t hp2 = hfpk(b0, b1);
            __half2 h22 = *(__half2*)&hp2;
            *(uint32_t*)&g_hh[(size_t)(rowA + 8) * F_OUT + col] = hp2;
            *(uint32_t*)&g_hl[(size_t)(rowA + 8) * F_OUT + col] =
                hfpk(b0 - __low2float(h22), b1 - __high2float(h22));
        }
    }
}

// ---------------------------------------------------------------------------
// Kernel 2: q = (h @ A) * log2e via 3-term compensated fp16 mma.
// B = A[head] (stored [d][e]) accessed with trans ldmatrix (V-path pattern).
// ---------------------------------------------------------------------------
#define MM2_HH  0
#define MM2_HL  10240
#define MM2_AH  20480
#define MM2_AL  29696
#define MM2_SZ  38912

__global__ __launch_bounds__(128) void k_mm2() {
    __shared__ __align__(16) char smem[MM2_SZ];
    const uint32_t sb = smem_u32(smem);
    const int tid = threadIdx.x, w = tid >> 5, lane = tid & 31;
    const int m0 = blockIdx.x * 128, head = blockIdx.y, hb = head * DH;
    const int lm = lane >> 3, lr = lane & 7;
    const int vKey = ((lm & 1) << 3) + lr;    // trans-B: k(d) row offset
    const int vD   = (lm >> 1) << 3;          // trans-B: n(e) col offset
    const int qRow = ((lm & 1) << 3) + lr;
    const int qCol = (lm >> 1) << 3;

    // load A[head] hi/lo once (64 rows x 128B, pitch 144)
    {
        const int r = tid & 63;
        const __half* as = (tid < 64) ? &g_ah[(size_t)head * DH * DH + r * DH]
                                      : &g_al[(size_t)head * DH * DH + r * DH];
        const uint32_t da = sb + ((tid < 64) ? MM2_AH : MM2_AL) + r * PITCH;
        #pragma unroll
        for (int c = 0; c < 8; c++) cpa16(da + c * 16, as + c * 8);
    }

    float oc[2][8][4] = {};

    for (int kc = 0; kc < 2; kc++) {
        {
            const __half* hh = &g_hh[(size_t)(m0 + tid) * F_OUT + hb + kc * 32];
            const __half* hl = &g_hl[(size_t)(m0 + tid) * F_OUT + hb + kc * 32];
            const uint32_t dh = sb + MM2_HH + tid * P80;
            const uint32_t dl = sb + MM2_HL + tid * P80;
            #pragma unroll
            for (int c = 0; c < 4; c++) {
                cpa16(dh + c * 16, hh + c * 8);
                cpa16(dl + c * 16, hl + c * 8);
            }
        }
        CP_COMMIT(); CP_WAIT0(); __syncthreads();

        uint32_t ah[4][4], al[4][4];
        #pragma unroll
        for (int m = 0; m < 2; m++) {
            const uint32_t bh = sb + MM2_HH + (w * 32 + m * 16 + qRow) * P80 + qCol * 2;
            const uint32_t bl = sb + MM2_HL + (w * 32 + m * 16 + qRow) * P80 + qCol * 2;
            #pragma unroll
            for (int s = 0; s < 2; s++) {
                ldsm4(bh + s * 32, ah[s * 2 + m][0], ah[s * 2 + m][1],
                                   ah[s * 2 + m][2], ah[s * 2 + m][3]);
                ldsm4(bl + s * 32, al[s * 2 + m][0], al[s * 2 + m][1],
                                   al[s * 2 + m][2], al[s * 2 + m][3]);
            }
        }
        #pragma unroll
        for (int s = 0; s < 2; s++) {
            const int kglob = kc * 32 + s * 16;
            #pragma unroll
            for (int u = 0; u < 4; u++) {
                uint32_t bh0, bh1, bh2, bh3, bl0, bl1, bl2, bl3;
                ldsm4t(sb + MM2_AH + (kglob + vKey) * PITCH + (u * 16 + vD) * 2, bh0, bh1, bh2, bh3);
                ldsm4t(sb + MM2_AL + (kglob + vKey) * PITCH + (u * 16 + vD) * 2, bl0, bl1, bl2, bl3);
                #pragma unroll
                for (int m = 0; m < 2; m++) {
                    mma16816(oc[m][2 * u],     ah[s * 2 + m], bh0, bh1);
                    mma16816(oc[m][2 * u],     al[s * 2 + m], bh0, bh1);
                    mma16816(oc[m][2 * u],     ah[s * 2 + m], bl0, bl1);
                    mma16816(oc[m][2 * u + 1], ah[s * 2 + m], bh2, bh3);
                    mma16816(oc[m][2 * u + 1], al[s * 2 + m], bh2, bh3);
                    mma16816(oc[m][2 * u + 1], ah[s * 2 + m], bl2, bl3);
                }
            }
        }
        __syncthreads();
    }

    const int g = lane >> 2, tg = lane & 3;
    #pragma unroll
    for (int m = 0; m < 2; m++) {
        const int rowA = m0 + w * 32 + m * 16 + g;
        #pragma unroll
        for (int j = 0; j < 8; j++) {
            const int col = hb + j * 8 + 2 * tg;
            *(uint32_t*)&g_qh[(size_t)rowA * F_OUT + col] =
                hfpk(oc[m][j][0] * LOG2E, oc[m][j][1] * LOG2E);
            *(uint32_t*)&g_qh[(size_t)(rowA + 8) * F_OUT + col] =
                hfpk(oc[m][j][2] * LOG2E, oc[m][j][3] * LOG2E);
        }
    }
}

// ---------------------------------------------------------------------------
// Kernel 3: pure-fp16 flash attention via mma.sync (fp32 accumulate).
// (unchanged from R11)
// ---------------------------------------------------------------------------
__global__ __launch_bounds__(128, 2) void k_attn(float* __restrict__ Out) {
    __shared__ __align__(16) char smem[SMEM_SZ];
    const uint32_t sb = smem_u32(smem);

    const int tid  = threadIdx.x;
    const int w    = tid >> 5;
    const int lane = tid & 31;
    const int head = blockIdx.y;
    const int q0   = blockIdx.x * QTILE;
    const int hb   = head * DH;

    const int lm = lane >> 3, lr = lane & 7;
    const int sKey = ((lm >> 1) << 3) + lr;
    const int sD   = (lm & 1) << 3;
    const int vKey = ((lm & 1) << 3) + lr;
    const int vD   = (lm >> 1) << 3;
    const int qRow = ((lm & 1) << 3) + lr;
    const int qCol = (lm >> 1) << 3;

    {
        const int r = tid;
        const __half* qh = &g_qh[(size_t)(q0 + r) * F_OUT + hb];
        const uint32_t d0 = sb + r * PITCH;
        #pragma unroll
        for (int c = 0; c < 8; c++) cpa16(d0 + c * 16, qh + c * 8);
    }
    CP_COMMIT();
    CP_WAIT0();
    __syncthreads();

    uint32_t qa[8][4];
    #pragma unroll
    for (int m = 0; m < 2; m++) {
        const uint32_t qb = sb + (w * 32 + m * 16 + qRow) * PITCH + qCol * 2;
        #pragma unroll
        for (int s = 0; s < 4; s++)
            ldsm4(qb + 16 * s * 2, qa[s * 2 + m][0], qa[s * 2 + m][1],
                                   qa[s * 2 + m][2], qa[s * 2 + m][3]);
    }
    __syncthreads();

    {
        const int r = tid >> 1, cb = (tid & 1) * 4;
        const uint32_t d0 = sb + r * PITCH + cb * 16;
        const __half* kh = &g_hh[(size_t)r * F_OUT + hb];
        #pragma unroll
        for (int c = 0; c < 4; c++) cpa16(d0 + c * 16, kh + (cb + c) * 8);
    }
    CP_COMMIT();

    float oc[2][8][4];
    #pragma unroll
    for (int m = 0; m < 2; m++)
        #pragma unroll
        for (int j = 0; j < 8; j++)
            #pragma unroll
            for (int k = 0; k < 4; k++) oc[m][j][k] = 0.f;
    float lsum[2][2] = {};

    for (int t = 0; t < NT; t++) {
        CP_WAIT0();
        __syncthreads();
        const uint32_t stg = sb + (t & 1) * STG;

        if (t + 1 < NT) {
            const int r = tid >> 1, cb = (tid & 1) * 4;
            const uint32_t d0 = sb + ((t + 1) & 1) * STG + r * PITCH + cb * 16;
            const __half* kh = &g_hh[(size_t)((t + 1) * KTILE + r) * F_OUT + hb];
            #pragma unroll
            for (int c = 0; c < 4; c++) cpa16(d0 + c * 16, kh + (cb + c) * 8);
        }
        CP_COMMIT();

        const uint32_t sAddr = stg + sKey * PITCH + sD * 2;
        const uint32_t vAddr = stg + vKey * PITCH + vD * 2;

        #pragma unroll
        for (int u = 0; u < 4; u++) {
            float sc[2][2][4];
            #pragma unroll
            for (int m = 0; m < 2; m++)
                #pragma unroll
                for (int k = 0; k < 4; k++) { sc[m][0][k] = 0.f; sc[m][1][k] = 0.f; }

            #pragma unroll
            for (int s = 0; s < 4; s++) {
                const uint32_t a = sAddr + (16 * u) * PITCH + (16 * s) * 2;
                uint32_t h0, h1, h2, h3;
                ldsm4(a, h0, h1, h2, h3);
                #pragma unroll
                for (int m = 0; m < 2; m++) {
                    mma16816(sc[m][0], qa[s * 2 + m], h0, h1);
                    mma16816(sc[m][1], qa[s * 2 + m], h2, h3);
                }
            }

            uint32_t pa[2][4];
            #pragma unroll
            for (int m = 0; m < 2; m++) {
                float e[8];
                #pragma unroll
                for (int k = 0; k < 4; k++) {
                    float v0 = sc[m][0][k];
                    e[k] = exp2_fast(fmaxf(v0, 0.2f * v0) - 6.0f);
                    float v1 = sc[m][1][k];
                    e[4 + k] = exp2_fast(fmaxf(v1, 0.2f * v1) - 6.0f);
                }
                lsum[m][0] += (e[0] + e[1]) + (e[4] + e[5]);
                lsum[m][1] += (e[2] + e[3]) + (e[6] + e[7]);

                pa[m][0] = hfpk(e[0], e[1]);
                pa[m][1] = hfpk(e[2], e[3]);
                pa[m][2] = hfpk(e[4], e[5]);
                pa[m][3] = hfpk(e[6], e[7]);
            }

            #pragma unroll
            for (int d = 0; d < 4; d++) {
                const uint32_t a = vAddr + (16 * u) * PITCH + (16 * d) * 2;
                uint32_t h0, h1, h2, h3;
                ldsm4t(a, h0, h1, h2, h3);
                #pragma unroll
                for (int m = 0; m < 2; m++) {
                    mma16816(oc[m][2 * d],     pa[m], h0, h1);
                    mma16816(oc[m][2 * d + 1], pa[m], h2, h3);
                }
            }
        }
    }

    const int g  = lane >> 2, tg = lane & 3;
    #pragma unroll
    for (int m = 0; m < 2; m++) {
        float lA = lsum[m][0], lB = lsum[m][1];
        lA += __shfl_xor_sync(0xffffffffu, lA, 1);
        lA += __shfl_xor_sync(0xffffffffu, lA, 2);
        lB += __shfl_xor_sync(0xffffffffu, lB, 1);
        lB += __shfl_xor_sync(0xffffffffu, lB, 2);
        const float invA = 1.0f / lA, invB = 1.0f / lB;

        const int rowA = q0 + w * 32 + m * 16 + g;
        float* outA = &Out[(size_t)rowA * F_OUT + hb + 2 * tg];
        float* outB = outA + 8 * F_OUT;
        #pragma unroll
        for (int j = 0; j < 8; j++) {
            *(float2*)(outA + 8 * j) = make_float2(oc[m][j][0] * invA, oc[m][j][1] * invA);
            *(float2*)(outB + 8 * j) = make_float2(oc[m][j][2] * invB, oc[m][j][3] * invB);
        }
    }
}

// ---------------------------------------------------------------------------
extern "C" void kernel_launch(void* const* d_in, const int* in_sizes, int n_in,
                              void* d_out, int out_size) {
    const float* x = (const float*)d_in[0];
    // d_in[1] = adj (unused by the reference forward)
    const float* W = (const float*)d_in[2];
    const float* A = (const float*)d_in[3];
    float* out = (float*)d_out;

    k_cvt<<<(N_X + N_W + N_A) / 512, 256>>>(x, W, A);
    k_mm1<<<dim3(N_NODES / 128, F_OUT / 64), 128>>>();
    k_mm2<<<dim3(N_NODES / 128, HEADS), 128>>>();
    k_attn<<<dim3(N_NODES / QTILE, HEADS), 128>>>(out);
}

// round 13
// speedup vs baseline: 2.4089x; 1.0273x over previous
#include <cuda_runtime.h>
#include <cuda_fp16.h>
#include <math.h>
#include <stdint.h>

#define N_NODES 4096
#define F_IN    256
#define F_OUT   512
#define HEADS   8
#define DH      64
#define LOG2E   1.4426950408889634f
#define MAGICF  12582912.0f          // 1.5 * 2^23

#define KTILE   64
#define NT      (N_NODES / KTILE)   // 64 key tiles
#define QTILE   128                 // q rows per block (32 per warp)
#define PITCH   144                 // bytes per 64-fp16 row (conflict-free)
#define STG     (KTILE * PITCH)     // 9216 bytes per K stage
#define QSM     (QTILE * PITCH)     // 18432 bytes Q region
#define ASMEM   (QSM + 2 * STG)     // 36864

#define N_X (N_NODES * F_IN)
#define N_W (F_OUT * F_IN)
#define N_A (HEADS * DH * DH)

typedef unsigned long long u64;

// ---------------- device scratch (no allocs allowed) ----------------
__device__ __align__(256) __half g_xh[N_X], g_xl[N_X];
__device__ __align__(256) __half g_wh[N_W], g_wl[N_W];
__device__ __align__(256) __half g_ah[N_A], g_al[N_A];
__device__ __align__(256) __half g_hh[N_NODES * F_OUT];   // fp16(h)  (K == V)
__device__ __align__(256) __half g_hl[N_NODES * F_OUT];   // fp16 residual of h
__device__ __align__(256) __half g_qh[N_NODES * F_OUT];   // fp16(q * log2e)

// ---------------- helpers ----------------
__device__ __forceinline__ uint32_t smem_u32(const void* p) {
    uint32_t a;
    asm("{ .reg .u64 t; cvta.to.shared.u64 t, %1; cvt.u32.u64 %0, t; }" : "=r"(a) : "l"(p));
    return a;
}
__device__ __forceinline__ uint32_t hfpk(float a, float b) {
    uint32_t r; asm("cvt.rn.f16x2.f32 %0, %1, %2;" : "=r"(r) : "f"(b), "f"(a)); return r;
}
__device__ __forceinline__ u64 pk2(float lo, float hi) {
    u64 r; asm("mov.b64 %0, {%1, %2};" : "=l"(r) : "f"(lo), "f"(hi)); return r;
}
__device__ __forceinline__ u64 dup2(float v) {
    u64 r; asm("mov.b64 %0, {%1, %1};" : "=l"(r) : "f"(v)); return r;
}
__device__ __forceinline__ void unp2(u64 v, float& lo, float& hi) {
    asm("mov.b64 {%0, %1}, %2;" : "=f"(lo), "=f"(hi) : "l"(v));
}
__device__ __forceinline__ u64 add2(u64 a, u64 b) {
    u64 r; asm("add.rn.f32x2 %0, %1, %2;" : "=l"(r) : "l"(a), "l"(b)); return r;
}
__device__ __forceinline__ u64 fma2_(u64 a, u64 b, u64 c) {
    u64 r; asm("fma.rn.f32x2 %0, %1, %2, %3;" : "=l"(r) : "l"(a), "l"(b), "l"(c)); return r;
}

// packed softmax: p = 2^(leaky(v) - 6) for a pair; accumulates lsum; returns fp16x2
__device__ __forceinline__ uint32_t softmax_pair(float c0, float c1, float& lacc) {
    u64 v2 = pk2(c0, c1);
    u64 y2 = fma2_(v2, dup2(0.6f), dup2(-6.0f));        // 0.6v - 6
    u64 a2 = v2 & 0x7FFFFFFF7FFFFFFFull;                // |v|
    y2 = fma2_(a2, dup2(0.4f), y2);                     // leaky - 6
    u64 fn2 = add2(y2, dup2(MAGICF));
    u64 t2  = fma2_(fn2, dup2(1.0f), dup2(-MAGICF));    // round(y)
    u64 f2  = fma2_(t2, dup2(-1.0f), y2);               // frac in [-0.5, 0.5]
    u64 p2  = fma2_(f2, dup2(0.00961813f), dup2(0.05550411f));
    p2 = fma2_(p2, f2, dup2(0.24022651f));
    p2 = fma2_(p2, f2, dup2(0.69314718f));
    p2 = fma2_(p2, f2, dup2(1.0f));
    float pf0, pf1, ff0, ff1;
    unp2(p2, pf0, pf1);
    unp2(fn2, ff0, ff1);
    float e0 = __int_as_float(__float_as_int(pf0) + (__float_as_int(ff0) << 23));
    float e1 = __int_as_float(__float_as_int(pf1) + (__float_as_int(ff1) << 23));
    lacc += e0 + e1;
    return hfpk(e0, e1);
}

__device__ __forceinline__ void cpa16(uint32_t dst, const void* src) {
    asm volatile("cp.async.cg.shared.global [%0], [%1], 16;" :: "r"(dst), "l"(src) : "memory");
}
#define CP_COMMIT() asm volatile("cp.async.commit_group;" ::: "memory")
#define CP_WAIT0()  asm volatile("cp.async.wait_group 0;" ::: "memory")

__device__ __forceinline__ void ldsm4(uint32_t a, uint32_t& r0, uint32_t& r1,
                                      uint32_t& r2, uint32_t& r3) {
    asm volatile("ldmatrix.sync.aligned.m8n8.x4.shared.b16 {%0,%1,%2,%3}, [%4];"
                 : "=r"(r0), "=r"(r1), "=r"(r2), "=r"(r3) : "r"(a));
}
__device__ __forceinline__ void ldsm4t(uint32_t a, uint32_t& r0, uint32_t& r1,
                                       uint32_t& r2, uint32_t& r3) {
    asm volatile("ldmatrix.sync.aligned.m8n8.x4.trans.shared.b16 {%0,%1,%2,%3}, [%4];"
                 : "=r"(r0), "=r"(r1), "=r"(r2), "=r"(r3) : "r"(a));
}
__device__ __forceinline__ void mma16816(float* c, const uint32_t* a, uint32_t b0, uint32_t b1) {
    asm volatile(
        "mma.sync.aligned.m16n8k16.row.col.f32.f16.f16.f32 "
        "{%0,%1,%2,%3}, {%4,%5,%6,%7}, {%8,%9}, {%0,%1,%2,%3};"
        : "+f"(c[0]), "+f"(c[1]), "+f"(c[2]), "+f"(c[3])
        : "r"(a[0]), "r"(a[1]), "r"(a[2]), "r"(a[3]), "r"(b0), "r"(b1));
}

// ---------------------------------------------------------------------------
// Kernel 0: convert x, W, A to fp16 hi/lo pairs.
// ---------------------------------------------------------------------------
__global__ __launch_bounds__(256) void k_cvt(const float* __restrict__ X,
                                             const float* __restrict__ W,
                                             const float* __restrict__ A) {
    const int i = (blockIdx.x * 256 + threadIdx.x) * 2;
    const float* src; __half *dh, *dl; int off;
    if (i < N_X)            { src = X; dh = g_xh; dl = g_xl; off = i; }
    else if (i < N_X + N_W) { src = W; dh = g_wh; dl = g_wl; off = i - N_X; }
    else                    { src = A; dh = g_ah; dl = g_al; off = i - N_X - N_W; }
    float2 v = *(const float2*)&src[off];
    uint32_t hp = hfpk(v.x, v.y);
    __half2 h2 = *(__half2*)&hp;
    uint32_t lp = hfpk(v.x - __low2float(h2), v.y - __high2float(h2));
    *(uint32_t*)&dh[off] = hp;
    *(uint32_t*)&dl[off] = lp;
}

// ---------------------------------------------------------------------------
// Kernel 1: h = x @ W^T via 3-term compensated fp16 mma. (unchanged from R12)
// ---------------------------------------------------------------------------
#define P80     80
#define MM1_XH  0
#define MM1_XL  10240
#define MM1_WH  20480
#define MM1_WL  25600
#define MM1_SZ  30720

__global__ __launch_bounds__(128) void k_mm1() {
    __shared__ __align__(16) char smem[MM1_SZ];
    const uint32_t sb = smem_u32(smem);
    const int tid = threadIdx.x, w = tid >> 5, lane = tid & 31;
    const int m0 = blockIdx.x * 128, o0 = blockIdx.y * 64;
    const int lm = lane >> 3, lr = lane & 7;
    const int sKey = ((lm >> 1) << 3) + lr;
    const int sD   = (lm & 1) << 3;
    const int qRow = ((lm & 1) << 3) + lr;
    const int qCol = (lm >> 1) << 3;

    float oc[2][8][4] = {};

    for (int kc = 0; kc < F_IN / 32; kc++) {
        const int k0 = kc * 32;
        {
            const __half* xh = &g_xh[(size_t)(m0 + tid) * F_IN + k0];
            const __half* xl = &g_xl[(size_t)(m0 + tid) * F_IN + k0];
            const uint32_t dxh = sb + MM1_XH + tid * P80;
            const uint32_t dxl = sb + MM1_XL + tid * P80;
            #pragma unroll
            for (int c = 0; c < 4; c++) {
                cpa16(dxh + c * 16, xh + c * 8);
                cpa16(dxl + c * 16, xl + c * 8);
            }
            const int r = tid & 63;
            const __half* ws = (tid < 64) ? &g_wh[(size_t)(o0 + r) * F_IN + k0]
                                          : &g_wl[(size_t)(o0 + r) * F_IN + k0];
            const uint32_t dw = sb + ((tid < 64) ? MM1_WH : MM1_WL) + r * P80;
            #pragma unroll
            for (int c = 0; c < 4; c++) cpa16(dw + c * 16, ws + c * 8);
        }
        CP_COMMIT(); CP_WAIT0(); __syncthreads();

        uint32_t ah[4][4], al[4][4];
        #pragma unroll
        for (int m = 0; m < 2; m++) {
            const uint32_t bh = sb + MM1_XH + (w * 32 + m * 16 + qRow) * P80 + qCol * 2;
            const uint32_t bl = sb + MM1_XL + (w * 32 + m * 16 + qRow) * P80 + qCol * 2;
            #pragma unroll
            for (int s = 0; s < 2; s++) {
                ldsm4(bh + s * 32, ah[s * 2 + m][0], ah[s * 2 + m][1],
                                   ah[s * 2 + m][2], ah[s * 2 + m][3]);
                ldsm4(bl + s * 32, al[s * 2 + m][0], al[s * 2 + m][1],
                                   al[s * 2 + m][2], al[s * 2 + m][3]);
            }
        }
        #pragma unroll
        for (int s = 0; s < 2; s++) {
            #pragma unroll
            for (int u = 0; u < 4; u++) {
                uint32_t bh0, bh1, bh2, bh3, bl0, bl1, bl2, bl3;
                ldsm4(sb + MM1_WH + (u * 16 + sKey) * P80 + s * 32 + sD * 2, bh0, bh1, bh2, bh3);
                ldsm4(sb + MM1_WL + (u * 16 + sKey) * P80 + s * 32 + sD * 2, bl0, bl1, bl2, bl3);
                #pragma unroll
                for (int m = 0; m < 2; m++) {
                    mma16816(oc[m][2 * u],     ah[s * 2 + m], bh0, bh1);
                    mma16816(oc[m][2 * u],     al[s * 2 + m], bh0, bh1);
                    mma16816(oc[m][2 * u],     ah[s * 2 + m], bl0, bl1);
                    mma16816(oc[m][2 * u + 1], ah[s * 2 + m], bh2, bh3);
                    mma16816(oc[m][2 * u + 1], al[s * 2 + m], bh2, bh3);
                    mma16816(oc[m][2 * u + 1], ah[s * 2 + m], bl2, bl3);
                }
            }
        }
        __syncthreads();
    }

    const int g = lane >> 2, tg = lane & 3;
    #pragma unroll
    for (int m = 0; m < 2; m++) {
        const int rowA = m0 + w * 32 + m * 16 + g;
        #pragma unroll
        for (int j = 0; j < 8; j++) {
            const int col = o0 + j * 8 + 2 * tg;
            float a0 = oc[m][j][0], a1 = oc[m][j][1];
            uint32_t hp = hfpk(a0, a1);
            __half2 h2 = *(__half2*)&hp;
            *(uint32_t*)&g_hh[(size_t)rowA * F_OUT + col] = hp;
            *(uint32_t*)&g_hl[(size_t)rowA * F_OUT + col] =
                hfpk(a0 - __low2float(h2), a1 - __high2float(h2));
            float b0 = oc[m][j][2], b1 = oc[m][j][3];
            uint32_t hp2 = hfpk(b0, b1);
            __half2 h22 = *(__half2*)&hp2;
            *(uint32_t*)&g_hh[(size_t)(rowA + 8) * F_OUT + col] = hp2;
            *(uint32_t*)&g_hl[(size_t)(rowA + 8) * F_OUT + col] =
                hfpk(b0 - __low2float(h22), b1 - __high2float(h22));
        }
    }
}

// ---------------------------------------------------------------------------
// Kernel 2: q = (h @ A) * log2e via 3-term compensated fp16 mma. (unchanged)
// ---------------------------------------------------------------------------
#define MM2_HH  0
#define MM2_HL  10240
#define MM2_AH  20480
#define MM2_AL  29696
#define MM2_SZ  38912

__global__ __launch_bounds__(128) void k_mm2() {
    __shared__ __align__(16) char smem[MM2_SZ];
    const uint32_t sb = smem_u32(smem);
    const int tid = threadIdx.x, w = tid >> 5, lane = tid & 31;
    const int m0 = blockIdx.x * 128, head = blockIdx.y, hb = head * DH;
    const int lm = lane >> 3, lr = lane & 7;
    const int vKey = ((lm & 1) << 3) + lr;
    const int vD   = (lm >> 1) << 3;
    const int qRow = ((lm & 1) << 3) + lr;
    const int qCol = (lm >> 1) << 3;

    {
        const int r = tid & 63;
        const __half* as = (tid < 64) ? &g_ah[(size_t)head * DH * DH + r * DH]
                                      : &g_al[(size_t)head * DH * DH + r * DH];
        const uint32_t da = sb + ((tid < 64) ? MM2_AH : MM2_AL) + r * PITCH;
        #pragma unroll
        for (int c = 0; c < 8; c++) cpa16(da + c * 16, as + c * 8);
    }

    float oc[2][8][4] = {};

    for (int kc = 0; kc < 2; kc++) {
        {
            const __half* hh = &g_hh[(size_t)(m0 + tid) * F_OUT + hb + kc * 32];
            const __half* hl = &g_hl[(size_t)(m0 + tid) * F_OUT + hb + kc * 32];
            const uint32_t dh = sb + MM2_HH + tid * P80;
            const uint32_t dl = sb + MM2_HL + tid * P80;
            #pragma unroll
            for (int c = 0; c < 4; c++) {
                cpa16(dh + c * 16, hh + c * 8);
                cpa16(dl + c * 16, hl + c * 8);
            }
        }
        CP_COMMIT(); CP_WAIT0(); __syncthreads();

        uint32_t ah[4][4], al[4][4];
        #pragma unroll
        for (int m = 0; m < 2; m++) {
            const uint32_t bh = sb + MM2_HH + (w * 32 + m * 16 + qRow) * P80 + qCol * 2;
            const uint32_t bl = sb + MM2_HL + (w * 32 + m * 16 + qRow) * P80 + qCol * 2;
            #pragma unroll
            for (int s = 0; s < 2; s++) {
                ldsm4(bh + s * 32, ah[s * 2 + m][0], ah[s * 2 + m][1],
                                   ah[s * 2 + m][2], ah[s * 2 + m][3]);
                ldsm4(bl + s * 32, al[s * 2 + m][0], al[s * 2 + m][1],
                                   al[s * 2 + m][2], al[s * 2 + m][3]);
            }
        }
        #pragma unroll
        for (int s = 0; s < 2; s++) {
            const int kglob = kc * 32 + s * 16;
            #pragma unroll
            for (int u = 0; u < 4; u++) {
                uint32_t bh0, bh1, bh2, bh3, bl0, bl1, bl2, bl3;
                ldsm4t(sb + MM2_AH + (kglob + vKey) * PITCH + (u * 16 + vD) * 2, bh0, bh1, bh2, bh3);
                ldsm4t(sb + MM2_AL + (kglob + vKey) * PITCH + (u * 16 + vD) * 2, bl0, bl1, bl2, bl3);
                #pragma unroll
                for (int m = 0; m < 2; m++) {
                    mma16816(oc[m][2 * u],     ah[s * 2 + m], bh0, bh1);
                    mma16816(oc[m][2 * u],     al[s * 2 + m], bh0, bh1);
                    mma16816(oc[m][2 * u],     ah[s * 2 + m], bl0, bl1);
                    mma16816(oc[m][2 * u + 1], ah[s * 2 + m], bh2, bh3);
                    mma16816(oc[m][2 * u + 1], al[s * 2 + m], bh2, bh3);
                    mma16816(oc[m][2 * u + 1], ah[s * 2 + m], bl2, bl3);
                }
            }
        }
        __syncthreads();
    }

    const int g = lane >> 2, tg = lane & 3;
    #pragma unroll
    for (int m = 0; m < 2; m++) {
        const int rowA = m0 + w * 32 + m * 16 + g;
        #pragma unroll
        for (int j = 0; j < 8; j++) {
            const int col = hb + j * 8 + 2 * tg;
            *(uint32_t*)&g_qh[(size_t)rowA * F_OUT + col] =
                hfpk(oc[m][j][0] * LOG2E, oc[m][j][1] * LOG2E);
            *(uint32_t*)&g_qh[(size_t)(rowA + 8) * F_OUT + col] =
                hfpk(oc[m][j][2] * LOG2E, oc[m][j][3] * LOG2E);
        }
    }
}

// ---------------------------------------------------------------------------
// Kernel 3: pure-fp16 flash attention; packed-f32x2 softmax; S pipelined ahead
// of softmax (double-buffered sc); Q fragments reloaded from dedicated smem.
// ---------------------------------------------------------------------------
#define S_BLOCK(uu)                                                              \
    do {                                                                         \
        const int par_ = (uu) & 1;                                               \
        _Pragma("unroll")                                                        \
        for (int m2 = 0; m2 < 2; m2++)                                           \
            _Pragma("unroll")                                                    \
            for (int k2 = 0; k2 < 4; k2++) {                                     \
                sc[par_][m2][0][k2] = 0.f; sc[par_][m2][1][k2] = 0.f;            \
            }                                                                    \
        _Pragma("unroll")                                                        \
        for (int s2 = 0; s2 < 4; s2++) {                                         \
            uint32_t kf0, kf1, kf2, kf3;                                         \
            ldsm4(sAddr + (16 * (uu)) * PITCH + (16 * s2) * 2,                   \
                  kf0, kf1, kf2, kf3);                                           \
            _Pragma("unroll")                                                    \
            for (int m2 = 0; m2 < 2; m2++) {                                     \
                uint32_t qv[4];                                                  \
                ldsm4(qBase + (m2 * 16) * PITCH + s2 * 32,                       \
                      qv[0], qv[1], qv[2], qv[3]);                               \
                mma16816(sc[par_][m2][0], qv, kf0, kf1);                         \
                mma16816(sc[par_][m2][1], qv, kf2, kf3);                         \
            }                                                                    \
        }                                                                        \
    } while (0)

__global__ __launch_bounds__(128, 2) void k_attn(float* __restrict__ Out) {
    __shared__ __align__(16) char smem[ASMEM];   // Q 18432 + 2 K stages 18432
    const uint32_t sb  = smem_u32(smem);
    const uint32_t sbK = sb + QSM;

    const int tid  = threadIdx.x;
    const int w    = tid >> 5;
    const int lane = tid & 31;
    const int head = blockIdx.y;
    const int q0   = blockIdx.x * QTILE;
    const int hb   = head * DH;

    const int lm = lane >> 3, lr = lane & 7;
    const int sKey = ((lm >> 1) << 3) + lr;
    const int sD   = (lm & 1) << 3;
    const int vKey = ((lm & 1) << 3) + lr;
    const int vD   = (lm >> 1) << 3;
    const int qRow = ((lm & 1) << 3) + lr;
    const int qCol = (lm >> 1) << 3;

    // ---- prologue: Q tile + K tile 0 in one cp.async group ----
    {
        const int r = tid;
        const __half* qh = &g_qh[(size_t)(q0 + r) * F_OUT + hb];
        const uint32_t d0 = sb + r * PITCH;
        #pragma unroll
        for (int c = 0; c < 8; c++) cpa16(d0 + c * 16, qh + c * 8);
        const int r2 = tid >> 1, cb = (tid & 1) * 4;
        const uint32_t dk = sbK + r2 * PITCH + cb * 16;
        const __half* kh = &g_hh[(size_t)r2 * F_OUT + hb];
        #pragma unroll
        for (int c = 0; c < 4; c++) cpa16(dk + c * 16, kh + (cb + c) * 8);
    }
    CP_COMMIT();

    const uint32_t qBase = sb + (w * 32 + qRow) * PITCH + qCol * 2;

    float oc[2][8][4];
    #pragma unroll
    for (int m = 0; m < 2; m++)
        #pragma unroll
        for (int j = 0; j < 8; j++)
            #pragma unroll
            for (int k = 0; k < 4; k++) oc[m][j][k] = 0.f;
    float lsum[2][2] = {};

    for (int t = 0; t < NT; t++) {
        CP_WAIT0();
        __syncthreads();
        const uint32_t stg = sbK + (t & 1) * STG;

        if (t + 1 < NT) {
            const int r = tid >> 1, cb = (tid & 1) * 4;
            const uint32_t d0 = sbK + ((t + 1) & 1) * STG + r * PITCH + cb * 16;
            const __half* kh = &g_hh[(size_t)((t + 1) * KTILE + r) * F_OUT + hb];
            #pragma unroll
            for (int c = 0; c < 4; c++) cpa16(d0 + c * 16, kh + (cb + c) * 8);
        }
        CP_COMMIT();

        const uint32_t sAddr = stg + sKey * PITCH + sD * 2;
        const uint32_t vAddr = stg + vKey * PITCH + vD * 2;

        float sc[2][2][2][4];   // [parity][m][nhalf][4]
        S_BLOCK(0);

        #pragma unroll
        for (int u = 0; u < 4; u++) {
            const int cur = u & 1;
            if (u < 3) S_BLOCK(u + 1);   // fill tensor pipe during softmax(u)

            // softmax on sc[cur] -> fp16 P fragments
            uint32_t pa[2][4];
            #pragma unroll
            for (int m = 0; m < 2; m++) {
                pa[m][0] = softmax_pair(sc[cur][m][0][0], sc[cur][m][0][1], lsum[m][0]);
                pa[m][1] = softmax_pair(sc[cur][m][0][2], sc[cur][m][0][3], lsum[m][1]);
                pa[m][2] = softmax_pair(sc[cur][m][1][0], sc[cur][m][1][1], lsum[m][0]);
                pa[m][3] = softmax_pair(sc[cur][m][1][2], sc[cur][m][1][3], lsum[m][1]);
            }

            // O += P V
            #pragma unroll
            for (int d = 0; d < 4; d++) {
                const uint32_t a = vAddr + (16 * u) * PITCH + (16 * d) * 2;
                uint32_t h0, h1, h2, h3;
                ldsm4t(a, h0, h1, h2, h3);
                #pragma unroll
                for (int m = 0; m < 2; m++) {
                    mma16816(oc[m][2 * d],     pa[m], h0, h1);
                    mma16816(oc[m][2 * d + 1], pa[m], h2, h3);
                }
            }
        }
    }

    // ---- reduce lsum across quad, normalize, write O ----
    const int g  = lane >> 2, tg = lane & 3;
    #pragma unroll
    for (int m = 0; m < 2; m++) {
        float lA = lsum[m][0], lB = lsum[m][1];
        lA += __shfl_xor_sync(0xffffffffu, lA, 1);
        lA += __shfl_xor_sync(0xffffffffu, lA, 2);
        lB += __shfl_xor_sync(0xffffffffu, lB, 1);
        lB += __shfl_xor_sync(0xffffffffu, lB, 2);
        const float invA = 1.0f / lA, invB = 1.0f / lB;

        const int rowA = q0 + w * 32 + m * 16 + g;
        float* outA = &Out[(size_t)rowA * F_OUT + hb + 2 * tg];
        float* outB = outA + 8 * F_OUT;
        #pragma unroll
        for (int j = 0; j < 8; j++) {
            *(float2*)(outA + 8 * j) = make_float2(oc[m][j][0] * invA, oc[m][j][1] * invA);
            *(float2*)(outB + 8 * j) = make_float2(oc[m][j][2] * invB, oc[m][j][3] * invB);
        }
    }
}

// ---------------------------------------------------------------------------
extern "C" void kernel_launch(void* const* d_in, const int* in_sizes, int n_in,
                              void* d_out, int out_size) {
    const float* x = (const float*)d_in[0];
    // d_in[1] = adj (unused by the reference forward)
    const float* W = (const float*)d_in[2];
    const float* A = (const float*)d_in[3];
    float* out = (float*)d_out;

    k_cvt<<<(N_X + N_W + N_A) / 512, 256>>>(x, W, A);
    k_mm1<<<dim3(N_NODES / 128, F_OUT / 64), 128>>>();
    k_mm2<<<dim3(N_NODES / 128, HEADS), 128>>>();
    k_attn<<<dim3(N_NODES / QTILE, HEADS), 128>>>(out);
}